// round 6
// baseline (speedup 1.0000x reference)
#include <cuda_runtime.h>
#include <cuda_fp16.h>
#include <cuda_bf16.h>

#define N_NODES 100000
#define N_EDGES 3200000
#define F_IN 35
#define KPAD 36
#define F_HID 64
#define F_OUT 2

// ---- scratch (static; no allocation allowed) ----
__device__ __align__(16) __half g_h1[N_NODES * F_HID];  // x@W1 in fp16
__device__ __align__(16) float  g_h2[N_NODES * F_OUT];  // layer-2 pre-agg features
__device__ float g_deg[N_NODES];
__device__ float g_dinv[N_NODES];
__device__ int   g_count[N_NODES];        // in-degree (no self-loop)
__device__ int   g_rowptr[N_NODES + 1];
__device__ int   g_rank[N_EDGES];         // per-edge slot within its dst segment
__device__ __align__(8) int2 g_csr[N_EDGES];  // (src, norm bits)

// ---------------- init: deg=1 (self loop), count=0 ----------------
__global__ void k_init(int n) {
    int i = blockIdx.x * blockDim.x + threadIdx.x;
    if (i < n) { g_deg[i] = 1.0f; g_count[i] = 0; }
}

// ---------------- degree + count scatter (rank captured) ----------------
__global__ void k_deg_scatter(const int* __restrict__ ei,
                              const float* __restrict__ ew, int ne) {
    int e = blockIdx.x * blockDim.x + threadIdx.x;
    if (e >= ne) return;
    int dst = ei[ne + e];
    atomicAdd(&g_deg[dst], ew[e]);
    g_rank[e] = atomicAdd(&g_count[dst], 1);
}

__global__ void k_dinv(int n) {
    int i = blockIdx.x * blockDim.x + threadIdx.x;
    if (i < n) {
        float d = g_deg[i];
        g_dinv[i] = (d > 0.0f) ? rsqrtf(d) : 0.0f;
    }
}

// ---------------- single-block exclusive scan: count -> rowptr ----------------
__global__ void k_scan(int n) {
    __shared__ int ssum[1024];
    int t = threadIdx.x;
    int chunk = (n + 1023) / 1024;
    int beg = t * chunk;
    int end = beg + chunk; if (end > n) end = n;
    int s = 0;
    for (int i = beg; i < end; i++) s += g_count[i];
    ssum[t] = s;
    __syncthreads();
    for (int o = 1; o < 1024; o <<= 1) {
        int add = (t >= o) ? ssum[t - o] : 0;
        __syncthreads();
        ssum[t] += add;
        __syncthreads();
    }
    int run = ssum[t] - s;  // exclusive offset at chunk start
    for (int i = beg; i < end; i++) {
        g_rowptr[i] = run;
        run += g_count[i];
    }
    if (t == 1023) g_rowptr[n] = ssum[1023];
}

// ---------------- CSR fill: packed (src, norm), no atomics ----------------
__global__ void k_csr_fill(const int* __restrict__ ei,
                           const float* __restrict__ ew, int ne) {
    int e = blockIdx.x * blockDim.x + threadIdx.x;
    if (e >= ne) return;
    int src = ei[e];
    int dst = ei[ne + e];
    float nrm = g_dinv[src] * ew[e] * g_dinv[dst];
    int pos = g_rowptr[dst] + g_rank[e];
    g_csr[pos] = make_int2(src, __float_as_int(nrm));
}

// ---------------- layer-1 GEMM: h1 = x@W1 (fp16). 2 rows/warp ----------------
__global__ void __launch_bounds__(256) k_gemm1(const float* __restrict__ x,
                                               const float* __restrict__ W1, int n) {
    __shared__ float2 sW2[KPAD][32];      // [k][lane] -> cols (2l, 2l+1); zero-padded k=35
    __shared__ float  sx[8][2][KPAD];     // 8 warps x 2 rows x 36
    int t = threadIdx.x, w = t >> 5, lane = t & 31;

    for (int i = t; i < KPAD * 32; i += 256) {
        int k = i >> 5, l = i & 31;
        float2 v = make_float2(0.f, 0.f);
        if (k < F_IN) { v.x = W1[k * F_HID + 2 * l]; v.y = W1[k * F_HID + 2 * l + 1]; }
        sW2[k][l] = v;
    }
    int row0 = blockIdx.x * 16 + w * 2;
#pragma unroll
    for (int r = 0; r < 2; r++) {
        int row = row0 + r;
        if (row < n) {
            sx[w][r][lane] = x[(size_t)row * F_IN + lane];
            if (lane < 4) sx[w][r][32 + lane] =
                (lane < F_IN - 32) ? x[(size_t)row * F_IN + 32 + lane] : 0.f;
        }
    }
    __syncthreads();
    if (row0 >= n) return;

    float acc00 = 0.f, acc01 = 0.f, acc10 = 0.f, acc11 = 0.f;
    const float4* sx40 = reinterpret_cast<const float4*>(sx[w][0]);
    const float4* sx41 = reinterpret_cast<const float4*>(sx[w][1]);
#pragma unroll
    for (int k4 = 0; k4 < KPAD / 4; k4++) {
        float4 x0 = sx40[k4], x1 = sx41[k4];
#pragma unroll
        for (int i = 0; i < 4; i++) {
            float2 wv = sW2[k4 * 4 + i][lane];
            float xv0 = (&x0.x)[i], xv1 = (&x1.x)[i];
            acc00 += xv0 * wv.x; acc01 += xv0 * wv.y;
            acc10 += xv1 * wv.x; acc11 += xv1 * wv.y;
        }
    }
    reinterpret_cast<__half2*>(g_h1 + (size_t)row0 * F_HID)[lane] =
        __floats2half2_rn(acc00, acc01);
    if (row0 + 1 < n)
        reinterpret_cast<__half2*>(g_h1 + (size_t)(row0 + 1) * F_HID)[lane] =
            __floats2half2_rn(acc10, acc11);
}

// ---------------- agg1 (CSR gather, smem-staged) + relu + b1 + GEMV W2 -> h2 ----
// warp per dst node; lane owns feature cols (2l, 2l+1)
__global__ void __launch_bounds__(256) k_agg1(const float* __restrict__ W2,
                                              const float* __restrict__ b1, int n) {
    __shared__ int2 stage[8][32];
    int wi = threadIdx.x >> 5;
    int lane = threadIdx.x & 31;
    int w = blockIdx.x * 8 + wi;
    if (w >= n) return;
    int beg = g_rowptr[w], end = g_rowptr[w + 1];
    float dv = g_dinv[w];
    float sl = dv * dv;

    float2 self = __half22float2(
        reinterpret_cast<const __half2*>(g_h1 + (size_t)w * F_HID)[lane]);
    float ax = sl * self.x, ay = sl * self.y;

    for (int j0 = beg; j0 < end; j0 += 32) {
        int j = j0 + lane;
        if (j < end) stage[wi][lane] = g_csr[j];
        __syncwarp();
        int cnt = end - j0; if (cnt > 32) cnt = 32;
        int i = 0;
        for (; i + 4 <= cnt; i += 4) {
            int2 e0 = stage[wi][i];
            int2 e1 = stage[wi][i + 1];
            int2 e2 = stage[wi][i + 2];
            int2 e3 = stage[wi][i + 3];
            float2 f0 = __half22float2(reinterpret_cast<const __half2*>(g_h1 + (size_t)e0.x * F_HID)[lane]);
            float2 f1 = __half22float2(reinterpret_cast<const __half2*>(g_h1 + (size_t)e1.x * F_HID)[lane]);
            float2 f2 = __half22float2(reinterpret_cast<const __half2*>(g_h1 + (size_t)e2.x * F_HID)[lane]);
            float2 f3 = __half22float2(reinterpret_cast<const __half2*>(g_h1 + (size_t)e3.x * F_HID)[lane]);
            float n0 = __int_as_float(e0.y), n1 = __int_as_float(e1.y);
            float n2 = __int_as_float(e2.y), n3 = __int_as_float(e3.y);
            ax += n0 * f0.x; ay += n0 * f0.y;
            ax += n1 * f1.x; ay += n1 * f1.y;
            ax += n2 * f2.x; ay += n2 * f2.y;
            ax += n3 * f3.x; ay += n3 * f3.y;
        }
        for (; i < cnt; i++) {
            int2 e0 = stage[wi][i];
            float2 f0 = __half22float2(reinterpret_cast<const __half2*>(g_h1 + (size_t)e0.x * F_HID)[lane]);
            float n0 = __int_as_float(e0.y);
            ax += n0 * f0.x; ay += n0 * f0.y;
        }
        __syncwarp();
    }

    // fused layer-2 input transform
    float h0 = fmaxf(ax + b1[2 * lane],     0.f);
    float h1 = fmaxf(ay + b1[2 * lane + 1], 0.f);
    float p0 = h0 * W2[(2 * lane) * 2 + 0] + h1 * W2[(2 * lane + 1) * 2 + 0];
    float p1 = h0 * W2[(2 * lane) * 2 + 1] + h1 * W2[(2 * lane + 1) * 2 + 1];
#pragma unroll
    for (int o = 16; o > 0; o >>= 1) {
        p0 += __shfl_xor_sync(0xFFFFFFFFu, p0, o);
        p1 += __shfl_xor_sync(0xFFFFFFFFu, p1, o);
    }
    if (lane == 0) {
        g_h2[w * 2 + 0] = p0;
        g_h2[w * 2 + 1] = p1;
    }
}

// ---------------- agg2 (CSR gather) + self + b2 + log_softmax -> out ----------------
__global__ void __launch_bounds__(256) k_agg2(const float* __restrict__ b2,
                                              float* __restrict__ out, int n) {
    int w = (blockIdx.x * blockDim.x + threadIdx.x) >> 5;
    int lane = threadIdx.x & 31;
    if (w >= n) return;
    int beg = g_rowptr[w], end = g_rowptr[w + 1];
    float a0 = 0.f, a1 = 0.f;
    for (int j = beg + lane; j < end; j += 32) {
        int2 e = g_csr[j];
        float nm = __int_as_float(e.y);
        float2 v = *reinterpret_cast<const float2*>(g_h2 + (size_t)e.x * 2);
        a0 += nm * v.x;
        a1 += nm * v.y;
    }
#pragma unroll
    for (int o = 16; o > 0; o >>= 1) {
        a0 += __shfl_xor_sync(0xFFFFFFFFu, a0, o);
        a1 += __shfl_xor_sync(0xFFFFFFFFu, a1, o);
    }
    if (lane == 0) {
        float dv = g_dinv[w];
        float sl = dv * dv;
        float2 hv = *reinterpret_cast<const float2*>(g_h2 + (size_t)w * 2);
        float A = a0 + sl * hv.x + b2[0];
        float B = a1 + sl * hv.y + b2[1];
        float m = fmaxf(A, B);
        float lse = m + logf(expf(A - m) + expf(B - m));
        out[w * 2 + 0] = A - lse;
        out[w * 2 + 1] = B - lse;
    }
}

extern "C" void kernel_launch(void* const* d_in, const int* in_sizes, int n_in,
                              void* d_out, int out_size) {
    const float* x  = (const float*)d_in[0];
    const int*   ei = (const int*)d_in[1];   // int32 (JAX x64 disabled)
    const float* ew = (const float*)d_in[2];
    const float* W1 = (const float*)d_in[3];
    const float* b1 = (const float*)d_in[4];
    const float* W2 = (const float*)d_in[5];
    const float* b2 = (const float*)d_in[6];
    float* out = (float*)d_out;

    const int n  = in_sizes[0] / F_IN;   // 100000
    const int ne = in_sizes[2];          // 3200000

    k_init<<<(n + 255) / 256, 256>>>(n);
    k_deg_scatter<<<(ne + 255) / 256, 256>>>(ei, ew, ne);
    k_dinv<<<(n + 255) / 256, 256>>>(n);
    k_scan<<<1, 1024>>>(n);
    k_csr_fill<<<(ne + 255) / 256, 256>>>(ei, ew, ne);
    k_gemm1<<<(n + 15) / 16, 256>>>(x, W1, n);
    k_agg1<<<(n + 7) / 8, 256>>>(W2, b1, n);
    k_agg2<<<(n * 32 + 255) / 256, 256>>>(b2, out, n);
}

// round 7
// speedup vs baseline: 1.4146x; 1.4146x over previous
#include <cuda_runtime.h>
#include <cuda_fp16.h>
#include <cuda_bf16.h>

#define N_NODES 100000
#define N_EDGES 3200000
#define F_IN 35
#define KPAD 36
#define F_HID 64
#define F_OUT 2
#define SCAN_CHUNK 512
#define SCAN_NBLK ((N_NODES + SCAN_CHUNK - 1) / SCAN_CHUNK)   // 196

// ---- scratch (static; no allocation allowed) ----
__device__ __align__(16) __half g_h1[N_NODES * F_HID];  // x@W1 in fp16
__device__ __align__(16) float  g_h2[N_NODES * F_OUT];  // layer-2 pre-agg features
__device__ float g_deg[N_NODES];
__device__ float g_dinv[N_NODES];
__device__ int   g_count[N_NODES];        // in-degree (no self-loop)
__device__ int   g_rowptr[N_NODES + 1];
__device__ int   g_rank[N_EDGES];         // per-edge slot within its dst segment
__device__ int   g_bsum[SCAN_NBLK];
__device__ int   g_boff[256];
__device__ __align__(8) int2 g_csr[N_EDGES];  // (src, norm bits)

// ---------------- init: deg=1 (self loop), count=0 ----------------
__global__ void k_init(int n) {
    int i = blockIdx.x * blockDim.x + threadIdx.x;
    if (i < n) { g_deg[i] = 1.0f; g_count[i] = 0; }
}

// ---------------- degree + count scatter (rank captured) ----------------
__global__ void k_deg_scatter(const int* __restrict__ ei,
                              const float* __restrict__ ew, int ne) {
    int e = blockIdx.x * blockDim.x + threadIdx.x;
    if (e >= ne) return;
    int dst = ei[ne + e];
    atomicAdd(&g_deg[dst], ew[e]);
    g_rank[e] = atomicAdd(&g_count[dst], 1);
}

__global__ void k_dinv(int n) {
    int i = blockIdx.x * blockDim.x + threadIdx.x;
    if (i < n) {
        float d = g_deg[i];
        g_dinv[i] = (d > 0.0f) ? rsqrtf(d) : 0.0f;
    }
}

// ---------------- 3-phase exclusive scan of g_count -> g_rowptr ----------------
__global__ void k_scan1(int n) {            // grid SCAN_NBLK, 512 thr: block sums
    __shared__ int sh[SCAN_CHUNK];
    int i = blockIdx.x * SCAN_CHUNK + threadIdx.x;
    sh[threadIdx.x] = (i < n) ? g_count[i] : 0;
    __syncthreads();
    for (int o = SCAN_CHUNK / 2; o > 0; o >>= 1) {
        if (threadIdx.x < o) sh[threadIdx.x] += sh[threadIdx.x + o];
        __syncthreads();
    }
    if (threadIdx.x == 0) g_bsum[blockIdx.x] = sh[0];
}

__global__ void k_scan2(int nblk, int n) {  // 1 block, 256 thr: scan of block sums
    __shared__ int sh[256];
    int t = threadIdx.x;
    int v = (t < nblk) ? g_bsum[t] : 0;
    sh[t] = v;
    __syncthreads();
    for (int o = 1; o < 256; o <<= 1) {
        int add = (t >= o) ? sh[t - o] : 0;
        __syncthreads();
        sh[t] += add;
        __syncthreads();
    }
    g_boff[t] = sh[t] - v;                  // exclusive
    if (t == nblk - 1) g_rowptr[n] = sh[t]; // total
}

__global__ void k_scan3(int n) {            // grid SCAN_NBLK, 512 thr: final rowptr
    __shared__ int sh[SCAN_CHUNK];
    int i = blockIdx.x * SCAN_CHUNK + threadIdx.x;
    int v = (i < n) ? g_count[i] : 0;
    sh[threadIdx.x] = v;
    __syncthreads();
    for (int o = 1; o < SCAN_CHUNK; o <<= 1) {
        int add = (threadIdx.x >= o) ? sh[threadIdx.x - o] : 0;
        __syncthreads();
        sh[threadIdx.x] += add;
        __syncthreads();
    }
    if (i < n)
        g_rowptr[i] = g_boff[blockIdx.x] + sh[threadIdx.x] - v;  // exclusive
}

// ---------------- CSR fill: packed (src, norm), no atomics ----------------
__global__ void k_csr_fill(const int* __restrict__ ei,
                           const float* __restrict__ ew, int ne) {
    int e = blockIdx.x * blockDim.x + threadIdx.x;
    if (e >= ne) return;
    int src = ei[e];
    int dst = ei[ne + e];
    float nrm = g_dinv[src] * ew[e] * g_dinv[dst];
    int pos = g_rowptr[dst] + g_rank[e];
    g_csr[pos] = make_int2(src, __float_as_int(nrm));
}

// ---------------- layer-1 GEMM: h1 = x@W1 (fp16). 2 rows/warp ----------------
__global__ void __launch_bounds__(256) k_gemm1(const float* __restrict__ x,
                                               const float* __restrict__ W1, int n) {
    __shared__ float2 sW2[KPAD][32];      // [k][lane] -> cols (2l, 2l+1); zero-padded k=35
    __shared__ float  sx[8][2][KPAD];     // 8 warps x 2 rows x 36
    int t = threadIdx.x, w = t >> 5, lane = t & 31;

    for (int i = t; i < KPAD * 32; i += 256) {
        int k = i >> 5, l = i & 31;
        float2 v = make_float2(0.f, 0.f);
        if (k < F_IN) { v.x = W1[k * F_HID + 2 * l]; v.y = W1[k * F_HID + 2 * l + 1]; }
        sW2[k][l] = v;
    }
    int row0 = blockIdx.x * 16 + w * 2;
#pragma unroll
    for (int r = 0; r < 2; r++) {
        int row = row0 + r;
        if (row < n) {
            sx[w][r][lane] = x[(size_t)row * F_IN + lane];
            if (lane < 4) sx[w][r][32 + lane] =
                (lane < F_IN - 32) ? x[(size_t)row * F_IN + 32 + lane] : 0.f;
        }
    }
    __syncthreads();
    if (row0 >= n) return;

    float acc00 = 0.f, acc01 = 0.f, acc10 = 0.f, acc11 = 0.f;
    const float4* sx40 = reinterpret_cast<const float4*>(sx[w][0]);
    const float4* sx41 = reinterpret_cast<const float4*>(sx[w][1]);
#pragma unroll
    for (int k4 = 0; k4 < KPAD / 4; k4++) {
        float4 x0 = sx40[k4], x1 = sx41[k4];
#pragma unroll
        for (int i = 0; i < 4; i++) {
            float2 wv = sW2[k4 * 4 + i][lane];
            float xv0 = (&x0.x)[i], xv1 = (&x1.x)[i];
            acc00 += xv0 * wv.x; acc01 += xv0 * wv.y;
            acc10 += xv1 * wv.x; acc11 += xv1 * wv.y;
        }
    }
    reinterpret_cast<__half2*>(g_h1 + (size_t)row0 * F_HID)[lane] =
        __floats2half2_rn(acc00, acc01);
    if (row0 + 1 < n)
        reinterpret_cast<__half2*>(g_h1 + (size_t)(row0 + 1) * F_HID)[lane] =
            __floats2half2_rn(acc10, acc11);
}

// ---------------- agg1 (CSR gather, smem-staged) + relu + b1 + GEMV W2 -> h2 ----
// warp per dst node; lane owns feature cols (2l, 2l+1)
__global__ void __launch_bounds__(256) k_agg1(const float* __restrict__ W2,
                                              const float* __restrict__ b1, int n) {
    __shared__ int2 stage[8][32];
    int wi = threadIdx.x >> 5;
    int lane = threadIdx.x & 31;
    int w = blockIdx.x * 8 + wi;
    if (w >= n) return;
    int beg = g_rowptr[w], end = g_rowptr[w + 1];
    float dv = g_dinv[w];
    float sl = dv * dv;

    float2 self = __half22float2(
        reinterpret_cast<const __half2*>(g_h1 + (size_t)w * F_HID)[lane]);
    float ax = sl * self.x, ay = sl * self.y;

    for (int j0 = beg; j0 < end; j0 += 32) {
        int j = j0 + lane;
        if (j < end) stage[wi][lane] = g_csr[j];
        __syncwarp();
        int cnt = end - j0; if (cnt > 32) cnt = 32;
        int i = 0;
        for (; i + 4 <= cnt; i += 4) {
            int2 e0 = stage[wi][i];
            int2 e1 = stage[wi][i + 1];
            int2 e2 = stage[wi][i + 2];
            int2 e3 = stage[wi][i + 3];
            float2 f0 = __half22float2(reinterpret_cast<const __half2*>(g_h1 + (size_t)e0.x * F_HID)[lane]);
            float2 f1 = __half22float2(reinterpret_cast<const __half2*>(g_h1 + (size_t)e1.x * F_HID)[lane]);
            float2 f2 = __half22float2(reinterpret_cast<const __half2*>(g_h1 + (size_t)e2.x * F_HID)[lane]);
            float2 f3 = __half22float2(reinterpret_cast<const __half2*>(g_h1 + (size_t)e3.x * F_HID)[lane]);
            float n0 = __int_as_float(e0.y), n1 = __int_as_float(e1.y);
            float n2 = __int_as_float(e2.y), n3 = __int_as_float(e3.y);
            ax += n0 * f0.x; ay += n0 * f0.y;
            ax += n1 * f1.x; ay += n1 * f1.y;
            ax += n2 * f2.x; ay += n2 * f2.y;
            ax += n3 * f3.x; ay += n3 * f3.y;
        }
        for (; i < cnt; i++) {
            int2 e0 = stage[wi][i];
            float2 f0 = __half22float2(reinterpret_cast<const __half2*>(g_h1 + (size_t)e0.x * F_HID)[lane]);
            float n0 = __int_as_float(e0.y);
            ax += n0 * f0.x; ay += n0 * f0.y;
        }
        __syncwarp();
    }

    // fused layer-2 input transform
    float h0 = fmaxf(ax + b1[2 * lane],     0.f);
    float h1 = fmaxf(ay + b1[2 * lane + 1], 0.f);
    float p0 = h0 * W2[(2 * lane) * 2 + 0] + h1 * W2[(2 * lane + 1) * 2 + 0];
    float p1 = h0 * W2[(2 * lane) * 2 + 1] + h1 * W2[(2 * lane + 1) * 2 + 1];
#pragma unroll
    for (int o = 16; o > 0; o >>= 1) {
        p0 += __shfl_xor_sync(0xFFFFFFFFu, p0, o);
        p1 += __shfl_xor_sync(0xFFFFFFFFu, p1, o);
    }
    if (lane == 0) {
        g_h2[w * 2 + 0] = p0;
        g_h2[w * 2 + 1] = p1;
    }
}

// ---------------- agg2 (CSR gather) + self + b2 + log_softmax -> out ----------------
__global__ void __launch_bounds__(256) k_agg2(const float* __restrict__ b2,
                                              float* __restrict__ out, int n) {
    int w = (blockIdx.x * blockDim.x + threadIdx.x) >> 5;
    int lane = threadIdx.x & 31;
    if (w >= n) return;
    int beg = g_rowptr[w], end = g_rowptr[w + 1];
    float a0 = 0.f, a1 = 0.f;
    for (int j = beg + lane; j < end; j += 32) {
        int2 e = g_csr[j];
        float nm = __int_as_float(e.y);
        float2 v = *reinterpret_cast<const float2*>(g_h2 + (size_t)e.x * 2);
        a0 += nm * v.x;
        a1 += nm * v.y;
    }
#pragma unroll
    for (int o = 16; o > 0; o >>= 1) {
        a0 += __shfl_xor_sync(0xFFFFFFFFu, a0, o);
        a1 += __shfl_xor_sync(0xFFFFFFFFu, a1, o);
    }
    if (lane == 0) {
        float dv = g_dinv[w];
        float sl = dv * dv;
        float2 hv = *reinterpret_cast<const float2*>(g_h2 + (size_t)w * 2);
        float A = a0 + sl * hv.x + b2[0];
        float B = a1 + sl * hv.y + b2[1];
        float m = fmaxf(A, B);
        float lse = m + logf(expf(A - m) + expf(B - m));
        out[w * 2 + 0] = A - lse;
        out[w * 2 + 1] = B - lse;
    }
}

extern "C" void kernel_launch(void* const* d_in, const int* in_sizes, int n_in,
                              void* d_out, int out_size) {
    const float* x  = (const float*)d_in[0];
    const int*   ei = (const int*)d_in[1];   // int32 (JAX x64 disabled)
    const float* ew = (const float*)d_in[2];
    const float* W1 = (const float*)d_in[3];
    const float* b1 = (const float*)d_in[4];
    const float* W2 = (const float*)d_in[5];
    const float* b2 = (const float*)d_in[6];
    float* out = (float*)d_out;

    const int n  = in_sizes[0] / F_IN;   // 100000
    const int ne = in_sizes[2];          // 3200000
    const int nblk = (n + SCAN_CHUNK - 1) / SCAN_CHUNK;

    k_init<<<(n + 255) / 256, 256>>>(n);
    k_deg_scatter<<<(ne + 255) / 256, 256>>>(ei, ew, ne);
    k_dinv<<<(n + 255) / 256, 256>>>(n);
    k_scan1<<<nblk, SCAN_CHUNK>>>(n);
    k_scan2<<<1, 256>>>(nblk, n);
    k_scan3<<<nblk, SCAN_CHUNK>>>(n);
    k_csr_fill<<<(ne + 255) / 256, 256>>>(ei, ew, ne);
    k_gemm1<<<(n + 15) / 16, 256>>>(x, W1, n);
    k_agg1<<<(n + 7) / 8, 256>>>(W2, b1, n);
    k_agg2<<<(n * 32 + 255) / 256, 256>>>(b2, out, n);
}

// round 8
// speedup vs baseline: 1.5845x; 1.1201x over previous
#include <cuda_runtime.h>
#include <cuda_fp16.h>
#include <cuda_bf16.h>

#define N_NODES 100000
#define N_EDGES 3200000
#define F_IN 35
#define KPAD 36
#define F_HID 64
#define F_OUT 2
#define SCAN_CHUNK 512
#define SCAN_NBLK ((N_NODES + SCAN_CHUNK - 1) / SCAN_CHUNK)   // 196
#define FIXP 268435456.0f   // 2^28
#define FIXP_INV (1.0f / 268435456.0f)

// ---- scratch (static; no allocation allowed) ----
__device__ __align__(16) __half g_h1[N_NODES * F_HID];  // x@W1 in fp16
__device__ __align__(16) float  g_h2[N_NODES * F_OUT];  // layer-2 pre-agg features
__device__ unsigned long long g_acc[N_NODES];  // hi24: count, lo40: sum(ew)*2^28
__device__ float g_dinv[N_NODES];
__device__ int   g_rowptr[N_NODES + 1];
__device__ int   g_rank[N_EDGES];         // per-edge slot within its dst segment
__device__ int   g_bsum[SCAN_NBLK];
__device__ int   g_boff[256];
__device__ __align__(8) int2 g_csr[N_EDGES];  // (src, norm bits)

// ---------------- fused: edge scatter (1 atomic/edge) || layer-1 GEMM ----------------
// blocks [0, nblk_sc): scatter; blocks [nblk_sc, ...): gemm1 (x@W1 -> fp16 h1)
__global__ void __launch_bounds__(256) k_scatter_gemm(
        const int* __restrict__ ei, const float* __restrict__ ew,
        const float* __restrict__ x, const float* __restrict__ W1,
        int n, int ne, int nblk_sc) {
    __shared__ float2 sW2[KPAD][32];
    __shared__ float  sx[8][2][KPAD];

    if (blockIdx.x < (unsigned)nblk_sc) {
        int e = blockIdx.x * 256 + threadIdx.x;
        if (e < ne) {
            int dst = ei[ne + e];
            unsigned long long v =
                (1ULL << 40) | (unsigned long long)(ew[e] * FIXP);
            unsigned long long old = atomicAdd(&g_acc[dst], v);
            g_rank[e] = (int)(old >> 40);
        }
        return;
    }

    // ---- gemm1 part ----
    int t = threadIdx.x, w = t >> 5, lane = t & 31;
    for (int i = t; i < KPAD * 32; i += 256) {
        int k = i >> 5, l = i & 31;
        float2 v = make_float2(0.f, 0.f);
        if (k < F_IN) { v.x = W1[k * F_HID + 2 * l]; v.y = W1[k * F_HID + 2 * l + 1]; }
        sW2[k][l] = v;
    }
    int row0 = (blockIdx.x - nblk_sc) * 16 + w * 2;
#pragma unroll
    for (int r = 0; r < 2; r++) {
        int row = row0 + r;
        if (row < n) {
            sx[w][r][lane] = x[(size_t)row * F_IN + lane];
            if (lane < 4) sx[w][r][32 + lane] =
                (lane < F_IN - 32) ? x[(size_t)row * F_IN + 32 + lane] : 0.f;
        }
    }
    __syncthreads();
    if (row0 >= n) return;

    float acc00 = 0.f, acc01 = 0.f, acc10 = 0.f, acc11 = 0.f;
    const float4* sx40 = reinterpret_cast<const float4*>(sx[w][0]);
    const float4* sx41 = reinterpret_cast<const float4*>(sx[w][1]);
#pragma unroll
    for (int k4 = 0; k4 < KPAD / 4; k4++) {
        float4 x0 = sx40[k4], x1 = sx41[k4];
#pragma unroll
        for (int i = 0; i < 4; i++) {
            float2 wv = sW2[k4 * 4 + i][lane];
            float xv0 = (&x0.x)[i], xv1 = (&x1.x)[i];
            acc00 += xv0 * wv.x; acc01 += xv0 * wv.y;
            acc10 += xv1 * wv.x; acc11 += xv1 * wv.y;
        }
    }
    reinterpret_cast<__half2*>(g_h1 + (size_t)row0 * F_HID)[lane] =
        __floats2half2_rn(acc00, acc01);
    if (row0 + 1 < n)
        reinterpret_cast<__half2*>(g_h1 + (size_t)(row0 + 1) * F_HID)[lane] =
            __floats2half2_rn(acc10, acc11);
}

// ---------------- scan phase 1 (+ fused dinv) ----------------
__global__ void k_scan1(int n) {
    __shared__ int sh[SCAN_CHUNK];
    int i = blockIdx.x * SCAN_CHUNK + threadIdx.x;
    int c = 0;
    if (i < n) {
        unsigned long long a = g_acc[i];
        c = (int)(a >> 40);
        float deg = 1.0f + (float)(a & ((1ULL << 40) - 1)) * FIXP_INV;
        g_dinv[i] = rsqrtf(deg);   // deg >= 1 always (self-loop)
    }
    sh[threadIdx.x] = c;
    __syncthreads();
    for (int o = SCAN_CHUNK / 2; o > 0; o >>= 1) {
        if (threadIdx.x < o) sh[threadIdx.x] += sh[threadIdx.x + o];
        __syncthreads();
    }
    if (threadIdx.x == 0) g_bsum[blockIdx.x] = sh[0];
}

__global__ void k_scan2(int nblk, int n) {  // 1 block, 256 thr
    __shared__ int sh[256];
    int t = threadIdx.x;
    int v = (t < nblk) ? g_bsum[t] : 0;
    sh[t] = v;
    __syncthreads();
    for (int o = 1; o < 256; o <<= 1) {
        int add = (t >= o) ? sh[t - o] : 0;
        __syncthreads();
        sh[t] += add;
        __syncthreads();
    }
    g_boff[t] = sh[t] - v;
    if (t == nblk - 1) g_rowptr[n] = sh[t];
}

__global__ void k_scan3(int n) {
    __shared__ int sh[SCAN_CHUNK];
    int i = blockIdx.x * SCAN_CHUNK + threadIdx.x;
    int v = (i < n) ? (int)(g_acc[i] >> 40) : 0;
    sh[threadIdx.x] = v;
    __syncthreads();
    for (int o = 1; o < SCAN_CHUNK; o <<= 1) {
        int add = (threadIdx.x >= o) ? sh[threadIdx.x - o] : 0;
        __syncthreads();
        sh[threadIdx.x] += add;
        __syncthreads();
    }
    if (i < n)
        g_rowptr[i] = g_boff[blockIdx.x] + sh[threadIdx.x] - v;  // exclusive
}

// ---------------- CSR fill: packed (src, norm), no atomics ----------------
__global__ void k_csr_fill(const int* __restrict__ ei,
                           const float* __restrict__ ew, int ne) {
    int e = blockIdx.x * blockDim.x + threadIdx.x;
    if (e >= ne) return;
    int src = ei[e];
    int dst = ei[ne + e];
    float nrm = g_dinv[src] * ew[e] * g_dinv[dst];
    int pos = g_rowptr[dst] + g_rank[e];
    g_csr[pos] = make_int2(src, __float_as_int(nrm));
}

// ---------------- agg1 (CSR gather, smem-staged) + relu + b1 + GEMV W2 -> h2 ----
__global__ void __launch_bounds__(256) k_agg1(const float* __restrict__ W2,
                                              const float* __restrict__ b1, int n) {
    __shared__ int2 stage[8][32];
    int wi = threadIdx.x >> 5;
    int lane = threadIdx.x & 31;
    int w = blockIdx.x * 8 + wi;
    if (w >= n) return;
    int beg = g_rowptr[w], end = g_rowptr[w + 1];
    float dv = g_dinv[w];
    float sl = dv * dv;

    float2 self = __half22float2(
        reinterpret_cast<const __half2*>(g_h1 + (size_t)w * F_HID)[lane]);
    float ax = sl * self.x, ay = sl * self.y;

    for (int j0 = beg; j0 < end; j0 += 32) {
        int j = j0 + lane;
        if (j < end) stage[wi][lane] = g_csr[j];
        __syncwarp();
        int cnt = end - j0; if (cnt > 32) cnt = 32;
        int i = 0;
        for (; i + 4 <= cnt; i += 4) {
            int2 e0 = stage[wi][i];
            int2 e1 = stage[wi][i + 1];
            int2 e2 = stage[wi][i + 2];
            int2 e3 = stage[wi][i + 3];
            float2 f0 = __half22float2(reinterpret_cast<const __half2*>(g_h1 + (size_t)e0.x * F_HID)[lane]);
            float2 f1 = __half22float2(reinterpret_cast<const __half2*>(g_h1 + (size_t)e1.x * F_HID)[lane]);
            float2 f2 = __half22float2(reinterpret_cast<const __half2*>(g_h1 + (size_t)e2.x * F_HID)[lane]);
            float2 f3 = __half22float2(reinterpret_cast<const __half2*>(g_h1 + (size_t)e3.x * F_HID)[lane]);
            float n0 = __int_as_float(e0.y), n1 = __int_as_float(e1.y);
            float n2 = __int_as_float(e2.y), n3 = __int_as_float(e3.y);
            ax += n0 * f0.x; ay += n0 * f0.y;
            ax += n1 * f1.x; ay += n1 * f1.y;
            ax += n2 * f2.x; ay += n2 * f2.y;
            ax += n3 * f3.x; ay += n3 * f3.y;
        }
        for (; i < cnt; i++) {
            int2 e0 = stage[wi][i];
            float2 f0 = __half22float2(reinterpret_cast<const __half2*>(g_h1 + (size_t)e0.x * F_HID)[lane]);
            float n0 = __int_as_float(e0.y);
            ax += n0 * f0.x; ay += n0 * f0.y;
        }
        __syncwarp();
    }

    float h0 = fmaxf(ax + b1[2 * lane],     0.f);
    float h1 = fmaxf(ay + b1[2 * lane + 1], 0.f);
    float p0 = h0 * W2[(2 * lane) * 2 + 0] + h1 * W2[(2 * lane + 1) * 2 + 0];
    float p1 = h0 * W2[(2 * lane) * 2 + 1] + h1 * W2[(2 * lane + 1) * 2 + 1];
#pragma unroll
    for (int o = 16; o > 0; o >>= 1) {
        p0 += __shfl_xor_sync(0xFFFFFFFFu, p0, o);
        p1 += __shfl_xor_sync(0xFFFFFFFFu, p1, o);
    }
    if (lane == 0) {
        g_h2[w * 2 + 0] = p0;
        g_h2[w * 2 + 1] = p1;
    }
}

// ---------------- agg2 (CSR gather) + self + b2 + log_softmax -> out ----------------
__global__ void __launch_bounds__(256) k_agg2(const float* __restrict__ b2,
                                              float* __restrict__ out, int n) {
    int w = (blockIdx.x * blockDim.x + threadIdx.x) >> 5;
    int lane = threadIdx.x & 31;
    if (w >= n) return;
    int beg = g_rowptr[w], end = g_rowptr[w + 1];
    float a0 = 0.f, a1 = 0.f;
    for (int j = beg + lane; j < end; j += 32) {
        int2 e = g_csr[j];
        float nm = __int_as_float(e.y);
        float2 v = *reinterpret_cast<const float2*>(g_h2 + (size_t)e.x * 2);
        a0 += nm * v.x;
        a1 += nm * v.y;
    }
#pragma unroll
    for (int o = 16; o > 0; o >>= 1) {
        a0 += __shfl_xor_sync(0xFFFFFFFFu, a0, o);
        a1 += __shfl_xor_sync(0xFFFFFFFFu, a1, o);
    }
    if (lane == 0) {
        float dv = g_dinv[w];
        float sl = dv * dv;
        float2 hv = *reinterpret_cast<const float2*>(g_h2 + (size_t)w * 2);
        float A = a0 + sl * hv.x + b2[0];
        float B = a1 + sl * hv.y + b2[1];
        float m = fmaxf(A, B);
        float lse = m + logf(expf(A - m) + expf(B - m));
        out[w * 2 + 0] = A - lse;
        out[w * 2 + 1] = B - lse;
    }
}

extern "C" void kernel_launch(void* const* d_in, const int* in_sizes, int n_in,
                              void* d_out, int out_size) {
    const float* x  = (const float*)d_in[0];
    const int*   ei = (const int*)d_in[1];   // int32 (JAX x64 disabled)
    const float* ew = (const float*)d_in[2];
    const float* W1 = (const float*)d_in[3];
    const float* b1 = (const float*)d_in[4];
    const float* W2 = (const float*)d_in[5];
    const float* b2 = (const float*)d_in[6];
    float* out = (float*)d_out;

    const int n  = in_sizes[0] / F_IN;   // 100000
    const int ne = in_sizes[2];          // 3200000
    const int nblk = (n + SCAN_CHUNK - 1) / SCAN_CHUNK;

    void* acc_ptr = nullptr;
    cudaGetSymbolAddress(&acc_ptr, g_acc);
    cudaMemsetAsync(acc_ptr, 0, (size_t)n * sizeof(unsigned long long));

    const int nblk_sc = (ne + 255) / 256;          // scatter blocks
    const int nblk_gm = (n + 15) / 16;             // gemm blocks
    k_scatter_gemm<<<nblk_sc + nblk_gm, 256>>>(ei, ew, x, W1, n, ne, nblk_sc);
    k_scan1<<<nblk, SCAN_CHUNK>>>(n);
    k_scan2<<<1, 256>>>(nblk, n);
    k_scan3<<<nblk, SCAN_CHUNK>>>(n);
    k_csr_fill<<<(ne + 255) / 256, 256>>>(ei, ew, ne);
    k_agg1<<<(n + 7) / 8, 256>>>(W2, b1, n);
    k_agg2<<<(n * 32 + 255) / 256, 256>>>(b2, out, n);
}

// round 9
// speedup vs baseline: 1.5889x; 1.0028x over previous
#include <cuda_runtime.h>
#include <cuda_fp16.h>
#include <cuda_bf16.h>

#define N_NODES 100000
#define N_EDGES 3200000
#define F_IN 35
#define KPAD 36
#define F_HID 64
#define F_OUT 2
#define FIXP 268435456.0f   // 2^28
#define FIXP_INV (1.0f / 268435456.0f)

// ---- scratch (static; no allocation allowed) ----
__device__ __align__(16) __half g_h1[N_NODES * F_HID];  // x@W1 in fp16
__device__ __align__(16) float  g_h2[N_NODES * F_OUT];  // layer-2 pre-agg features
__device__ unsigned long long g_acc[N_NODES];  // hi24: count, lo40: sum(ew)*2^28
__device__ float g_dinv[N_NODES];
__device__ __align__(8) int2 g_seg[N_NODES];   // (beg, end) of node's CSR segment
__device__ int   g_cursor;                     // global CSR allocation cursor
__device__ int   g_rank[N_EDGES];              // per-edge slot within its dst segment
__device__ __align__(8) int2 g_csr[N_EDGES];   // (src, norm bits)

// ---------------- fused: edge scatter (1 atomic/edge) || layer-1 GEMM ----------------
__global__ void __launch_bounds__(256) k_scatter_gemm(
        const int* __restrict__ ei, const float* __restrict__ ew,
        const float* __restrict__ x, const float* __restrict__ W1,
        int n, int ne, int nblk_sc) {
    __shared__ float2 sW2[KPAD][32];
    __shared__ float  sx[8][2][KPAD];

    if (blockIdx.x < (unsigned)nblk_sc) {
        int e = blockIdx.x * 256 + threadIdx.x;
        if (e < ne) {
            int dst = ei[ne + e];
            unsigned long long v =
                (1ULL << 40) | (unsigned long long)(ew[e] * FIXP);
            unsigned long long old = atomicAdd(&g_acc[dst], v);
            g_rank[e] = (int)(old >> 40);
        }
        return;
    }

    // ---- gemm1 part ----
    int t = threadIdx.x, w = t >> 5, lane = t & 31;
    for (int i = t; i < KPAD * 32; i += 256) {
        int k = i >> 5, l = i & 31;
        float2 v = make_float2(0.f, 0.f);
        if (k < F_IN) { v.x = W1[k * F_HID + 2 * l]; v.y = W1[k * F_HID + 2 * l + 1]; }
        sW2[k][l] = v;
    }
    int row0 = (blockIdx.x - nblk_sc) * 16 + w * 2;
#pragma unroll
    for (int r = 0; r < 2; r++) {
        int row = row0 + r;
        if (row < n) {
            sx[w][r][lane] = x[(size_t)row * F_IN + lane];
            if (lane < 4) sx[w][r][32 + lane] =
                (lane < F_IN - 32) ? x[(size_t)row * F_IN + 32 + lane] : 0.f;
        }
    }
    __syncthreads();
    if (row0 >= n) return;

    float acc00 = 0.f, acc01 = 0.f, acc10 = 0.f, acc11 = 0.f;
    const float4* sx40 = reinterpret_cast<const float4*>(sx[w][0]);
    const float4* sx41 = reinterpret_cast<const float4*>(sx[w][1]);
#pragma unroll
    for (int k4 = 0; k4 < KPAD / 4; k4++) {
        float4 x0 = sx40[k4], x1 = sx41[k4];
#pragma unroll
        for (int i = 0; i < 4; i++) {
            float2 wv = sW2[k4 * 4 + i][lane];
            float xv0 = (&x0.x)[i], xv1 = (&x1.x)[i];
            acc00 += xv0 * wv.x; acc01 += xv0 * wv.y;
            acc10 += xv1 * wv.x; acc11 += xv1 * wv.y;
        }
    }
    reinterpret_cast<__half2*>(g_h1 + (size_t)row0 * F_HID)[lane] =
        __floats2half2_rn(acc00, acc01);
    if (row0 + 1 < n)
        reinterpret_cast<__half2*>(g_h1 + (size_t)(row0 + 1) * F_HID)[lane] =
            __floats2half2_rn(acc10, acc11);
}

// ---------------- base allocation: dinv + block-scan + cursor atomic ----------------
// Segment placement is order-free; each block claims a contiguous range via one atomic.
__global__ void __launch_bounds__(256) k_base(int n) {
    __shared__ int swarp[8];
    __shared__ int sbase;
    int t = threadIdx.x, lane = t & 31, wid = t >> 5;
    int i = blockIdx.x * 256 + t;
    int c = 0;
    if (i < n) {
        unsigned long long a = g_acc[i];
        c = (int)(a >> 40);
        float deg = 1.0f + (float)(a & ((1ULL << 40) - 1)) * FIXP_INV;
        g_dinv[i] = rsqrtf(deg);
    }
    // warp inclusive scan
    int v = c;
#pragma unroll
    for (int o = 1; o < 32; o <<= 1) {
        int u = __shfl_up_sync(0xFFFFFFFFu, v, o);
        if (lane >= o) v += u;
    }
    if (lane == 31) swarp[wid] = v;
    __syncthreads();
    if (wid == 0) {
        int s = (lane < 8) ? swarp[lane] : 0;
#pragma unroll
        for (int o = 1; o < 8; o <<= 1) {
            int u = __shfl_up_sync(0xFFFFFFFFu, s, o);
            if (lane >= o) s += u;
        }
        if (lane < 8) swarp[lane] = s;       // inclusive warp totals
        if (lane == 7) sbase = atomicAdd(&g_cursor, s);  // block total
    }
    __syncthreads();
    int excl = v - c + (wid > 0 ? swarp[wid - 1] : 0);
    if (i < n) {
        int beg = sbase + excl;
        g_seg[i] = make_int2(beg, beg + c);
    }
}

// ---------------- CSR fill: packed (src, norm), no atomics ----------------
__global__ void k_csr_fill(const int* __restrict__ ei,
                           const float* __restrict__ ew, int ne) {
    int e = blockIdx.x * blockDim.x + threadIdx.x;
    if (e >= ne) return;
    int src = ei[e];
    int dst = ei[ne + e];
    float nrm = g_dinv[src] * ew[e] * g_dinv[dst];
    int pos = g_seg[dst].x + g_rank[e];
    g_csr[pos] = make_int2(src, __float_as_int(nrm));
}

// ---------------- agg1 (CSR gather, smem-staged, unroll 8) + relu + b1 + W2 GEMV ----
__global__ void __launch_bounds__(256) k_agg1(const float* __restrict__ W2,
                                              const float* __restrict__ b1, int n) {
    __shared__ int2 stage[8][32];
    int wi = threadIdx.x >> 5;
    int lane = threadIdx.x & 31;
    int w = blockIdx.x * 8 + wi;
    if (w >= n) return;
    int2 seg = g_seg[w];
    int beg = seg.x, end = seg.y;
    float dv = g_dinv[w];
    float sl = dv * dv;

    float2 self = __half22float2(
        reinterpret_cast<const __half2*>(g_h1 + (size_t)w * F_HID)[lane]);
    float ax = sl * self.x, ay = sl * self.y;

    for (int j0 = beg; j0 < end; j0 += 32) {
        int j = j0 + lane;
        if (j < end) stage[wi][lane] = g_csr[j];
        __syncwarp();
        int cnt = end - j0; if (cnt > 32) cnt = 32;
        int i = 0;
        for (; i + 8 <= cnt; i += 8) {
            int2 e0 = stage[wi][i];
            int2 e1 = stage[wi][i + 1];
            int2 e2 = stage[wi][i + 2];
            int2 e3 = stage[wi][i + 3];
            int2 e4 = stage[wi][i + 4];
            int2 e5 = stage[wi][i + 5];
            int2 e6 = stage[wi][i + 6];
            int2 e7 = stage[wi][i + 7];
            float2 f0 = __half22float2(reinterpret_cast<const __half2*>(g_h1 + (size_t)e0.x * F_HID)[lane]);
            float2 f1 = __half22float2(reinterpret_cast<const __half2*>(g_h1 + (size_t)e1.x * F_HID)[lane]);
            float2 f2 = __half22float2(reinterpret_cast<const __half2*>(g_h1 + (size_t)e2.x * F_HID)[lane]);
            float2 f3 = __half22float2(reinterpret_cast<const __half2*>(g_h1 + (size_t)e3.x * F_HID)[lane]);
            float2 f4 = __half22float2(reinterpret_cast<const __half2*>(g_h1 + (size_t)e4.x * F_HID)[lane]);
            float2 f5 = __half22float2(reinterpret_cast<const __half2*>(g_h1 + (size_t)e5.x * F_HID)[lane]);
            float2 f6 = __half22float2(reinterpret_cast<const __half2*>(g_h1 + (size_t)e6.x * F_HID)[lane]);
            float2 f7 = __half22float2(reinterpret_cast<const __half2*>(g_h1 + (size_t)e7.x * F_HID)[lane]);
            ax += __int_as_float(e0.y) * f0.x; ay += __int_as_float(e0.y) * f0.y;
            ax += __int_as_float(e1.y) * f1.x; ay += __int_as_float(e1.y) * f1.y;
            ax += __int_as_float(e2.y) * f2.x; ay += __int_as_float(e2.y) * f2.y;
            ax += __int_as_float(e3.y) * f3.x; ay += __int_as_float(e3.y) * f3.y;
            ax += __int_as_float(e4.y) * f4.x; ay += __int_as_float(e4.y) * f4.y;
            ax += __int_as_float(e5.y) * f5.x; ay += __int_as_float(e5.y) * f5.y;
            ax += __int_as_float(e6.y) * f6.x; ay += __int_as_float(e6.y) * f6.y;
            ax += __int_as_float(e7.y) * f7.x; ay += __int_as_float(e7.y) * f7.y;
        }
        for (; i < cnt; i++) {
            int2 e0 = stage[wi][i];
            float2 f0 = __half22float2(reinterpret_cast<const __half2*>(g_h1 + (size_t)e0.x * F_HID)[lane]);
            float n0 = __int_as_float(e0.y);
            ax += n0 * f0.x; ay += n0 * f0.y;
        }
        __syncwarp();
    }

    float h0 = fmaxf(ax + b1[2 * lane],     0.f);
    float h1 = fmaxf(ay + b1[2 * lane + 1], 0.f);
    float p0 = h0 * W2[(2 * lane) * 2 + 0] + h1 * W2[(2 * lane + 1) * 2 + 0];
    float p1 = h0 * W2[(2 * lane) * 2 + 1] + h1 * W2[(2 * lane + 1) * 2 + 1];
#pragma unroll
    for (int o = 16; o > 0; o >>= 1) {
        p0 += __shfl_xor_sync(0xFFFFFFFFu, p0, o);
        p1 += __shfl_xor_sync(0xFFFFFFFFu, p1, o);
    }
    if (lane == 0) {
        g_h2[w * 2 + 0] = p0;
        g_h2[w * 2 + 1] = p1;
    }
}

// ---------------- agg2 (CSR gather) + self + b2 + log_softmax -> out ----------------
__global__ void __launch_bounds__(256) k_agg2(const float* __restrict__ b2,
                                              float* __restrict__ out, int n) {
    int w = (blockIdx.x * blockDim.x + threadIdx.x) >> 5;
    int lane = threadIdx.x & 31;
    if (w >= n) return;
    int2 seg = g_seg[w];
    float a0 = 0.f, a1 = 0.f;
    for (int j = seg.x + lane; j < seg.y; j += 32) {
        int2 e = g_csr[j];
        float nm = __int_as_float(e.y);
        float2 v = *reinterpret_cast<const float2*>(g_h2 + (size_t)e.x * 2);
        a0 += nm * v.x;
        a1 += nm * v.y;
    }
#pragma unroll
    for (int o = 16; o > 0; o >>= 1) {
        a0 += __shfl_xor_sync(0xFFFFFFFFu, a0, o);
        a1 += __shfl_xor_sync(0xFFFFFFFFu, a1, o);
    }
    if (lane == 0) {
        float dv = g_dinv[w];
        float sl = dv * dv;
        float2 hv = *reinterpret_cast<const float2*>(g_h2 + (size_t)w * 2);
        float A = a0 + sl * hv.x + b2[0];
        float B = a1 + sl * hv.y + b2[1];
        float m = fmaxf(A, B);
        float lse = m + logf(expf(A - m) + expf(B - m));
        out[w * 2 + 0] = A - lse;
        out[w * 2 + 1] = B - lse;
    }
}

extern "C" void kernel_launch(void* const* d_in, const int* in_sizes, int n_in,
                              void* d_out, int out_size) {
    const float* x  = (const float*)d_in[0];
    const int*   ei = (const int*)d_in[1];   // int32 (JAX x64 disabled)
    const float* ew = (const float*)d_in[2];
    const float* W1 = (const float*)d_in[3];
    const float* b1 = (const float*)d_in[4];
    const float* W2 = (const float*)d_in[5];
    const float* b2 = (const float*)d_in[6];
    float* out = (float*)d_out;

    const int n  = in_sizes[0] / F_IN;   // 100000
    const int ne = in_sizes[2];          // 3200000

    void* acc_ptr = nullptr;
    cudaGetSymbolAddress(&acc_ptr, g_acc);
    cudaMemsetAsync(acc_ptr, 0, (size_t)n * sizeof(unsigned long long));
    void* cur_ptr = nullptr;
    cudaGetSymbolAddress(&cur_ptr, g_cursor);
    cudaMemsetAsync(cur_ptr, 0, sizeof(int));

    const int nblk_sc = (ne + 255) / 256;
    const int nblk_gm = (n + 15) / 16;
    k_scatter_gemm<<<nblk_sc + nblk_gm, 256>>>(ei, ew, x, W1, n, ne, nblk_sc);
    k_base<<<(n + 255) / 256, 256>>>(n);
    k_csr_fill<<<(ne + 255) / 256, 256>>>(ei, ew, ne);
    k_agg1<<<(n + 7) / 8, 256>>>(W2, b1, n);
    k_agg2<<<(n * 32 + 255) / 256, 256>>>(b2, out, n);
}

// round 10
// speedup vs baseline: 1.6316x; 1.0269x over previous
#include <cuda_runtime.h>
#include <cuda_fp16.h>
#include <cuda_bf16.h>

#define N_NODES 100000
#define N_EDGES 3200000
#define F_IN 35
#define KPAD 36
#define F_HID 64
#define F_OUT 2
#define FIXP 268435456.0f   // 2^28
#define FIXP_INV (1.0f / 268435456.0f)

// ---- scratch (static; no allocation allowed) ----
__device__ __align__(16) __half g_h1[N_NODES * F_HID];  // x@W1 in fp16
__device__ __align__(16) float  g_h2[N_NODES * F_OUT];  // layer-2 pre-agg features
__device__ unsigned long long g_acc[N_NODES];  // hi24: count, lo40: sum(ew)*2^28
__device__ float g_dinv[N_NODES];
__device__ __align__(8) int2 g_seg[N_NODES];   // (beg, end) of node's CSR segment
__device__ int   g_cursor;                     // global CSR allocation cursor
__device__ __align__(16) int g_rank[N_EDGES];  // per-edge slot within its dst segment
__device__ __align__(8) int2 g_csr[N_EDGES];   // (src, dinv[src]*ew bits)

// ---------------- fused: edge scatter (4 edges/thread) || layer-1 GEMM ----------------
__global__ void __launch_bounds__(256) k_scatter_gemm(
        const int* __restrict__ ei, const float* __restrict__ ew,
        const float* __restrict__ x, const float* __restrict__ W1,
        int n, int ne, int nblk_sc) {
    __shared__ float2 sW2[KPAD][32];
    __shared__ float  sx[8][2][KPAD];

    if (blockIdx.x < (unsigned)nblk_sc) {
        int e0 = (blockIdx.x * 256 + threadIdx.x) * 4;
        if (e0 + 3 < ne) {
            float4 w4 = *reinterpret_cast<const float4*>(ew + e0);  // e0 % 4 == 0
            int d0 = ei[ne + e0], d1 = ei[ne + e0 + 1];
            int d2 = ei[ne + e0 + 2], d3 = ei[ne + e0 + 3];
            unsigned long long o0 = atomicAdd(&g_acc[d0], (1ULL << 40) | (unsigned long long)(w4.x * FIXP));
            unsigned long long o1 = atomicAdd(&g_acc[d1], (1ULL << 40) | (unsigned long long)(w4.y * FIXP));
            unsigned long long o2 = atomicAdd(&g_acc[d2], (1ULL << 40) | (unsigned long long)(w4.z * FIXP));
            unsigned long long o3 = atomicAdd(&g_acc[d3], (1ULL << 40) | (unsigned long long)(w4.w * FIXP));
            *reinterpret_cast<int4*>(g_rank + e0) =
                make_int4((int)(o0 >> 40), (int)(o1 >> 40), (int)(o2 >> 40), (int)(o3 >> 40));
        } else {
            for (int e = e0; e < ne; e++) {
                int dst = ei[ne + e];
                unsigned long long old = atomicAdd(&g_acc[dst],
                    (1ULL << 40) | (unsigned long long)(ew[e] * FIXP));
                g_rank[e] = (int)(old >> 40);
            }
        }
        return;
    }

    // ---- gemm1 part ----
    int t = threadIdx.x, w = t >> 5, lane = t & 31;
    for (int i = t; i < KPAD * 32; i += 256) {
        int k = i >> 5, l = i & 31;
        float2 v = make_float2(0.f, 0.f);
        if (k < F_IN) { v.x = W1[k * F_HID + 2 * l]; v.y = W1[k * F_HID + 2 * l + 1]; }
        sW2[k][l] = v;
    }
    int row0 = (blockIdx.x - nblk_sc) * 16 + w * 2;
#pragma unroll
    for (int r = 0; r < 2; r++) {
        int row = row0 + r;
        if (row < n) {
            sx[w][r][lane] = x[(size_t)row * F_IN + lane];
            if (lane < 4) sx[w][r][32 + lane] =
                (lane < F_IN - 32) ? x[(size_t)row * F_IN + 32 + lane] : 0.f;
        }
    }
    __syncthreads();
    if (row0 >= n) return;

    float acc00 = 0.f, acc01 = 0.f, acc10 = 0.f, acc11 = 0.f;
    const float4* sx40 = reinterpret_cast<const float4*>(sx[w][0]);
    const float4* sx41 = reinterpret_cast<const float4*>(sx[w][1]);
#pragma unroll
    for (int k4 = 0; k4 < KPAD / 4; k4++) {
        float4 x0 = sx40[k4], x1 = sx41[k4];
#pragma unroll
        for (int i = 0; i < 4; i++) {
            float2 wv = sW2[k4 * 4 + i][lane];
            float xv0 = (&x0.x)[i], xv1 = (&x1.x)[i];
            acc00 += xv0 * wv.x; acc01 += xv0 * wv.y;
            acc10 += xv1 * wv.x; acc11 += xv1 * wv.y;
        }
    }
    reinterpret_cast<__half2*>(g_h1 + (size_t)row0 * F_HID)[lane] =
        __floats2half2_rn(acc00, acc01);
    if (row0 + 1 < n)
        reinterpret_cast<__half2*>(g_h1 + (size_t)(row0 + 1) * F_HID)[lane] =
            __floats2half2_rn(acc10, acc11);
}

// ---------------- base allocation: dinv + block-scan + cursor atomic ----------------
__global__ void __launch_bounds__(256) k_base(int n) {
    __shared__ int swarp[8];
    __shared__ int sbase;
    int t = threadIdx.x, lane = t & 31, wid = t >> 5;
    int i = blockIdx.x * 256 + t;
    int c = 0;
    if (i < n) {
        unsigned long long a = g_acc[i];
        c = (int)(a >> 40);
        float deg = 1.0f + (float)(a & ((1ULL << 40) - 1)) * FIXP_INV;
        g_dinv[i] = rsqrtf(deg);
    }
    int v = c;
#pragma unroll
    for (int o = 1; o < 32; o <<= 1) {
        int u = __shfl_up_sync(0xFFFFFFFFu, v, o);
        if (lane >= o) v += u;
    }
    if (lane == 31) swarp[wid] = v;
    __syncthreads();
    if (wid == 0) {
        int s = (lane < 8) ? swarp[lane] : 0;
#pragma unroll
        for (int o = 1; o < 8; o <<= 1) {
            int u = __shfl_up_sync(0xFFFFFFFFu, s, o);
            if (lane >= o) s += u;
        }
        if (lane < 8) swarp[lane] = s;
        if (lane == 7) sbase = atomicAdd(&g_cursor, s);
    }
    __syncthreads();
    int excl = v - c + (wid > 0 ? swarp[wid - 1] : 0);
    if (i < n) {
        int beg = sbase + excl;
        g_seg[i] = make_int2(beg, beg + c);
    }
}

// ---------------- CSR fill (4 edges/thread): (src, dinv[src]*ew) ----------------
__global__ void __launch_bounds__(256) k_csr_fill(const int* __restrict__ ei,
                                                  const float* __restrict__ ew, int ne) {
    int e0 = (blockIdx.x * 256 + threadIdx.x) * 4;
    if (e0 + 3 < ne) {
        int4   s4 = *reinterpret_cast<const int4*>(ei + e0);       // e0 % 4 == 0
        float4 w4 = *reinterpret_cast<const float4*>(ew + e0);
        int4   r4 = *reinterpret_cast<const int4*>(g_rank + e0);
        int d0 = ei[ne + e0], d1 = ei[ne + e0 + 1];
        int d2 = ei[ne + e0 + 2], d3 = ei[ne + e0 + 3];
        float n0 = g_dinv[s4.x] * w4.x;
        float n1 = g_dinv[s4.y] * w4.y;
        float n2 = g_dinv[s4.z] * w4.z;
        float n3 = g_dinv[s4.w] * w4.w;
        g_csr[g_seg[d0].x + r4.x] = make_int2(s4.x, __float_as_int(n0));
        g_csr[g_seg[d1].x + r4.y] = make_int2(s4.y, __float_as_int(n1));
        g_csr[g_seg[d2].x + r4.z] = make_int2(s4.z, __float_as_int(n2));
        g_csr[g_seg[d3].x + r4.w] = make_int2(s4.w, __float_as_int(n3));
    } else {
        for (int e = e0; e < ne; e++) {
            int src = ei[e];
            int dst = ei[ne + e];
            float nrm = g_dinv[src] * ew[e];
            g_csr[g_seg[dst].x + g_rank[e]] = make_int2(src, __float_as_int(nrm));
        }
    }
}

// ---------------- agg1 (CSR gather, smem-staged) + relu + b1 + W2 GEMV ----------------
// agg = dv * sum(nrm'_e * h1[src_e]) + dv^2 * h1[w]   (dst-side dinv deferred)
__global__ void __launch_bounds__(256) k_agg1(const float* __restrict__ W2,
                                              const float* __restrict__ b1, int n) {
    __shared__ int2 stage[8][32];
    int wi = threadIdx.x >> 5;
    int lane = threadIdx.x & 31;
    int w = blockIdx.x * 8 + wi;
    if (w >= n) return;
    int2 seg = g_seg[w];
    int beg = seg.x, end = seg.y;
    float dv = g_dinv[w];
    float sl = dv * dv;

    float2 self = __half22float2(
        reinterpret_cast<const __half2*>(g_h1 + (size_t)w * F_HID)[lane]);
    float ax = 0.f, ay = 0.f;

    for (int j0 = beg; j0 < end; j0 += 32) {
        int j = j0 + lane;
        if (j < end) stage[wi][lane] = g_csr[j];
        __syncwarp();
        int cnt = end - j0; if (cnt > 32) cnt = 32;
        int i = 0;
        for (; i + 8 <= cnt; i += 8) {
            int2 e0 = stage[wi][i];
            int2 e1 = stage[wi][i + 1];
            int2 e2 = stage[wi][i + 2];
            int2 e3 = stage[wi][i + 3];
            int2 e4 = stage[wi][i + 4];
            int2 e5 = stage[wi][i + 5];
            int2 e6 = stage[wi][i + 6];
            int2 e7 = stage[wi][i + 7];
            float2 f0 = __half22float2(reinterpret_cast<const __half2*>(g_h1 + (size_t)e0.x * F_HID)[lane]);
            float2 f1 = __half22float2(reinterpret_cast<const __half2*>(g_h1 + (size_t)e1.x * F_HID)[lane]);
            float2 f2 = __half22float2(reinterpret_cast<const __half2*>(g_h1 + (size_t)e2.x * F_HID)[lane]);
            float2 f3 = __half22float2(reinterpret_cast<const __half2*>(g_h1 + (size_t)e3.x * F_HID)[lane]);
            float2 f4 = __half22float2(reinterpret_cast<const __half2*>(g_h1 + (size_t)e4.x * F_HID)[lane]);
            float2 f5 = __half22float2(reinterpret_cast<const __half2*>(g_h1 + (size_t)e5.x * F_HID)[lane]);
            float2 f6 = __half22float2(reinterpret_cast<const __half2*>(g_h1 + (size_t)e6.x * F_HID)[lane]);
            float2 f7 = __half22float2(reinterpret_cast<const __half2*>(g_h1 + (size_t)e7.x * F_HID)[lane]);
            ax += __int_as_float(e0.y) * f0.x; ay += __int_as_float(e0.y) * f0.y;
            ax += __int_as_float(e1.y) * f1.x; ay += __int_as_float(e1.y) * f1.y;
            ax += __int_as_float(e2.y) * f2.x; ay += __int_as_float(e2.y) * f2.y;
            ax += __int_as_float(e3.y) * f3.x; ay += __int_as_float(e3.y) * f3.y;
            ax += __int_as_float(e4.y) * f4.x; ay += __int_as_float(e4.y) * f4.y;
            ax += __int_as_float(e5.y) * f5.x; ay += __int_as_float(e5.y) * f5.y;
            ax += __int_as_float(e6.y) * f6.x; ay += __int_as_float(e6.y) * f6.y;
            ax += __int_as_float(e7.y) * f7.x; ay += __int_as_float(e7.y) * f7.y;
        }
        for (; i < cnt; i++) {
            int2 e0 = stage[wi][i];
            float2 f0 = __half22float2(reinterpret_cast<const __half2*>(g_h1 + (size_t)e0.x * F_HID)[lane]);
            float n0 = __int_as_float(e0.y);
            ax += n0 * f0.x; ay += n0 * f0.y;
        }
        __syncwarp();
    }

    ax = dv * ax + sl * self.x;
    ay = dv * ay + sl * self.y;

    float h0 = fmaxf(ax + b1[2 * lane],     0.f);
    float h1 = fmaxf(ay + b1[2 * lane + 1], 0.f);
    float p0 = h0 * W2[(2 * lane) * 2 + 0] + h1 * W2[(2 * lane + 1) * 2 + 0];
    float p1 = h0 * W2[(2 * lane) * 2 + 1] + h1 * W2[(2 * lane + 1) * 2 + 1];
#pragma unroll
    for (int o = 16; o > 0; o >>= 1) {
        p0 += __shfl_xor_sync(0xFFFFFFFFu, p0, o);
        p1 += __shfl_xor_sync(0xFFFFFFFFu, p1, o);
    }
    if (lane == 0) {
        g_h2[w * 2 + 0] = p0;
        g_h2[w * 2 + 1] = p1;
    }
}

// ---------------- agg2 (CSR gather) + self + b2 + log_softmax -> out ----------------
__global__ void __launch_bounds__(256) k_agg2(const float* __restrict__ b2,
                                              float* __restrict__ out, int n) {
    int w = (blockIdx.x * blockDim.x + threadIdx.x) >> 5;
    int lane = threadIdx.x & 31;
    if (w >= n) return;
    int2 seg = g_seg[w];
    float a0 = 0.f, a1 = 0.f;
    for (int j = seg.x + lane; j < seg.y; j += 32) {
        int2 e = g_csr[j];
        float nm = __int_as_float(e.y);
        float2 v = *reinterpret_cast<const float2*>(g_h2 + (size_t)e.x * 2);
        a0 += nm * v.x;
        a1 += nm * v.y;
    }
#pragma unroll
    for (int o = 16; o > 0; o >>= 1) {
        a0 += __shfl_xor_sync(0xFFFFFFFFu, a0, o);
        a1 += __shfl_xor_sync(0xFFFFFFFFu, a1, o);
    }
    if (lane == 0) {
        float dv = g_dinv[w];
        float sl = dv * dv;
        float2 hv = *reinterpret_cast<const float2*>(g_h2 + (size_t)w * 2);
        float A = dv * a0 + sl * hv.x + b2[0];
        float B = dv * a1 + sl * hv.y + b2[1];
        float m = fmaxf(A, B);
        float lse = m + logf(expf(A - m) + expf(B - m));
        out[w * 2 + 0] = A - lse;
        out[w * 2 + 1] = B - lse;
    }
}

extern "C" void kernel_launch(void* const* d_in, const int* in_sizes, int n_in,
                              void* d_out, int out_size) {
    const float* x  = (const float*)d_in[0];
    const int*   ei = (const int*)d_in[1];   // int32 (JAX x64 disabled)
    const float* ew = (const float*)d_in[2];
    const float* W1 = (const float*)d_in[3];
    const float* b1 = (const float*)d_in[4];
    const float* W2 = (const float*)d_in[5];
    const float* b2 = (const float*)d_in[6];
    float* out = (float*)d_out;

    const int n  = in_sizes[0] / F_IN;   // 100000
    const int ne = in_sizes[2];          // 3200000

    void* acc_ptr = nullptr;
    cudaGetSymbolAddress(&acc_ptr, g_acc);
    cudaMemsetAsync(acc_ptr, 0, (size_t)n * sizeof(unsigned long long));
    void* cur_ptr = nullptr;
    cudaGetSymbolAddress(&cur_ptr, g_cursor);
    cudaMemsetAsync(cur_ptr, 0, sizeof(int));

    const int nq = (ne + 3) / 4;                   // 4 edges per scatter thread
    const int nblk_sc = (nq + 255) / 256;
    const int nblk_gm = (n + 15) / 16;
    k_scatter_gemm<<<nblk_sc + nblk_gm, 256>>>(ei, ew, x, W1, n, ne, nblk_sc);
    k_base<<<(n + 255) / 256, 256>>>(n);
    k_csr_fill<<<(nq + 255) / 256, 256>>>(ei, ew, ne);
    k_agg1<<<(n + 7) / 8, 256>>>(W2, b1, n);
    k_agg2<<<(n * 32 + 255) / 256, 256>>>(b2, out, n);
}

// round 11
// speedup vs baseline: 1.6603x; 1.0176x over previous
#include <cuda_runtime.h>
#include <cuda_fp16.h>
#include <cuda_bf16.h>

#define N_NODES 100000
#define N_EDGES 3200000
#define F_IN 35
#define KPAD 36
#define F_HID 64
#define F_OUT 2
#define FIXP 268435456.0f   // 2^28
#define FIXP_INV (1.0f / 268435456.0f)

// ---- scratch (static; no allocation allowed; zero-initialized at load) ----
__device__ __align__(16) __half g_h1[N_NODES * F_HID];  // x@W1 fp16; scaled to dinv*h1 by k_base
__device__ __align__(16) float  g_h2[N_NODES * F_OUT];  // dinv * (layer-2 features)
__device__ unsigned long long g_acc[N_NODES];  // hi24: count, lo40: sum(ew)*2^28 (self-cleaned)
__device__ float g_dinv[N_NODES];
__device__ __align__(8) int2 g_seg[N_NODES];   // (beg, end) of node's CSR segment
__device__ int   g_cursor;                     // CSR cursor (self-cleaned by k_csr_fill)
__device__ __align__(16) int g_rank[N_EDGES];  // per-edge slot within its dst segment
__device__ __align__(8) int2 g_csr[N_EDGES];   // (src, ew bits)

// ---------------- fused: edge scatter (4 edges/thread) || layer-1 GEMM ----------------
__global__ void __launch_bounds__(256) k_scatter_gemm(
        const int* __restrict__ ei, const float* __restrict__ ew,
        const float* __restrict__ x, const float* __restrict__ W1,
        int n, int ne, int nblk_sc) {
    __shared__ float2 sW2[KPAD][32];
    __shared__ float  sx[8][2][KPAD];

    if (blockIdx.x < (unsigned)nblk_sc) {
        int e0 = (blockIdx.x * 256 + threadIdx.x) * 4;
        if (e0 + 3 < ne) {
            float4 w4 = *reinterpret_cast<const float4*>(ew + e0);  // e0 % 4 == 0
            int d0 = ei[ne + e0], d1 = ei[ne + e0 + 1];
            int d2 = ei[ne + e0 + 2], d3 = ei[ne + e0 + 3];
            unsigned long long o0 = atomicAdd(&g_acc[d0], (1ULL << 40) | (unsigned long long)(w4.x * FIXP));
            unsigned long long o1 = atomicAdd(&g_acc[d1], (1ULL << 40) | (unsigned long long)(w4.y * FIXP));
            unsigned long long o2 = atomicAdd(&g_acc[d2], (1ULL << 40) | (unsigned long long)(w4.z * FIXP));
            unsigned long long o3 = atomicAdd(&g_acc[d3], (1ULL << 40) | (unsigned long long)(w4.w * FIXP));
            *reinterpret_cast<int4*>(g_rank + e0) =
                make_int4((int)(o0 >> 40), (int)(o1 >> 40), (int)(o2 >> 40), (int)(o3 >> 40));
        } else {
            for (int e = e0; e < ne; e++) {
                int dst = ei[ne + e];
                unsigned long long old = atomicAdd(&g_acc[dst],
                    (1ULL << 40) | (unsigned long long)(ew[e] * FIXP));
                g_rank[e] = (int)(old >> 40);
            }
        }
        return;
    }

    // ---- gemm1 part ----
    int t = threadIdx.x, w = t >> 5, lane = t & 31;
    for (int i = t; i < KPAD * 32; i += 256) {
        int k = i >> 5, l = i & 31;
        float2 v = make_float2(0.f, 0.f);
        if (k < F_IN) { v.x = W1[k * F_HID + 2 * l]; v.y = W1[k * F_HID + 2 * l + 1]; }
        sW2[k][l] = v;
    }
    int row0 = (blockIdx.x - nblk_sc) * 16 + w * 2;
#pragma unroll
    for (int r = 0; r < 2; r++) {
        int row = row0 + r;
        if (row < n) {
            sx[w][r][lane] = x[(size_t)row * F_IN + lane];
            if (lane < 4) sx[w][r][32 + lane] =
                (lane < F_IN - 32) ? x[(size_t)row * F_IN + 32 + lane] : 0.f;
        }
    }
    __syncthreads();
    if (row0 >= n) return;

    float acc00 = 0.f, acc01 = 0.f, acc10 = 0.f, acc11 = 0.f;
    const float4* sx40 = reinterpret_cast<const float4*>(sx[w][0]);
    const float4* sx41 = reinterpret_cast<const float4*>(sx[w][1]);
#pragma unroll
    for (int k4 = 0; k4 < KPAD / 4; k4++) {
        float4 x0 = sx40[k4], x1 = sx41[k4];
#pragma unroll
        for (int i = 0; i < 4; i++) {
            float2 wv = sW2[k4 * 4 + i][lane];
            float xv0 = (&x0.x)[i], xv1 = (&x1.x)[i];
            acc00 += xv0 * wv.x; acc01 += xv0 * wv.y;
            acc10 += xv1 * wv.x; acc11 += xv1 * wv.y;
        }
    }
    reinterpret_cast<__half2*>(g_h1 + (size_t)row0 * F_HID)[lane] =
        __floats2half2_rn(acc00, acc01);
    if (row0 + 1 < n)
        reinterpret_cast<__half2*>(g_h1 + (size_t)(row0 + 1) * F_HID)[lane] =
            __floats2half2_rn(acc10, acc11);
}

// ---- base: dinv + seg alloc (block scan + cursor atomic) + h1 *= dinv + acc clear ----
__global__ void __launch_bounds__(256) k_base(int n) {
    __shared__ int swarp[8];
    __shared__ int sbase;
    __shared__ float sdinv[256];
    int t = threadIdx.x, lane = t & 31, wid = t >> 5;
    int i = blockIdx.x * 256 + t;
    int c = 0;
    if (i < n) {
        unsigned long long a = g_acc[i];
        g_acc[i] = 0ULL;                    // self-clean for next replay
        c = (int)(a >> 40);
        float deg = 1.0f + (float)(a & ((1ULL << 40) - 1)) * FIXP_INV;
        float dv = rsqrtf(deg);
        g_dinv[i] = dv;
        sdinv[t] = dv;
    }
    int v = c;
#pragma unroll
    for (int o = 1; o < 32; o <<= 1) {
        int u = __shfl_up_sync(0xFFFFFFFFu, v, o);
        if (lane >= o) v += u;
    }
    if (lane == 31) swarp[wid] = v;
    __syncthreads();
    if (wid == 0) {
        int s = (lane < 8) ? swarp[lane] : 0;
#pragma unroll
        for (int o = 1; o < 8; o <<= 1) {
            int u = __shfl_up_sync(0xFFFFFFFFu, s, o);
            if (lane >= o) s += u;
        }
        if (lane < 8) swarp[lane] = s;
        if (lane == 7) sbase = atomicAdd(&g_cursor, s);
    }
    __syncthreads();
    int excl = v - c + (wid > 0 ? swarp[wid - 1] : 0);
    if (i < n) {
        int beg = sbase + excl;
        g_seg[i] = make_int2(beg, beg + c);
    }
    // scale this block's h1 rows by dinv: h1' = dinv * h1 (warp per row, coalesced)
    int nodebase = blockIdx.x * 256;
#pragma unroll 4
    for (int k = 0; k < 32; k++) {
        int node = nodebase + wid * 32 + k;
        if (node < n) {
            float dvn = sdinv[wid * 32 + k];
            __half2* p = reinterpret_cast<__half2*>(g_h1 + (size_t)node * F_HID);
            float2 f = __half22float2(p[lane]);
            p[lane] = __floats2half2_rn(dvn * f.x, dvn * f.y);
        }
    }
}

// ---------------- CSR fill (4 edges/thread): (src, ew) — pure stream+scatter ----------------
__global__ void __launch_bounds__(256) k_csr_fill(const int* __restrict__ ei,
                                                  const float* __restrict__ ew, int ne) {
    if (blockIdx.x == 0 && threadIdx.x == 0) g_cursor = 0;   // self-clean for next replay
    int e0 = (blockIdx.x * 256 + threadIdx.x) * 4;
    if (e0 + 3 < ne) {
        int4   s4 = *reinterpret_cast<const int4*>(ei + e0);       // e0 % 4 == 0
        float4 w4 = *reinterpret_cast<const float4*>(ew + e0);
        int4   r4 = *reinterpret_cast<const int4*>(g_rank + e0);
        int d0 = ei[ne + e0], d1 = ei[ne + e0 + 1];
        int d2 = ei[ne + e0 + 2], d3 = ei[ne + e0 + 3];
        g_csr[g_seg[d0].x + r4.x] = make_int2(s4.x, __float_as_int(w4.x));
        g_csr[g_seg[d1].x + r4.y] = make_int2(s4.y, __float_as_int(w4.y));
        g_csr[g_seg[d2].x + r4.z] = make_int2(s4.z, __float_as_int(w4.z));
        g_csr[g_seg[d3].x + r4.w] = make_int2(s4.w, __float_as_int(w4.w));
    } else {
        for (int e = e0; e < ne; e++) {
            int src = ei[e];
            int dst = ei[ne + e];
            g_csr[g_seg[dst].x + g_rank[e]] = make_int2(src, __float_as_int(ew[e]));
        }
    }
}

// ---------------- agg1: agg = dv*(Σ ew*h1'[src] + h1'[w]); h2' = dv*GEMV ----------------
__global__ void __launch_bounds__(256) k_agg1(const float* __restrict__ W2,
                                              const float* __restrict__ b1, int n) {
    __shared__ int2 stage[8][32];
    int wi = threadIdx.x >> 5;
    int lane = threadIdx.x & 31;
    int w = blockIdx.x * 8 + wi;
    if (w >= n) return;
    int2 seg = g_seg[w];
    int beg = seg.x, end = seg.y;
    float dv = g_dinv[w];

    float2 self = __half22float2(
        reinterpret_cast<const __half2*>(g_h1 + (size_t)w * F_HID)[lane]);
    float ax = self.x, ay = self.y;   // h1'[w] = dv*h1[w]; x dv below gives dv^2*h1

    for (int j0 = beg; j0 < end; j0 += 32) {
        int j = j0 + lane;
        if (j < end) stage[wi][lane] = g_csr[j];
        __syncwarp();
        int cnt = end - j0; if (cnt > 32) cnt = 32;
        int i = 0;
        for (; i + 8 <= cnt; i += 8) {
            int2 e0 = stage[wi][i];
            int2 e1 = stage[wi][i + 1];
            int2 e2 = stage[wi][i + 2];
            int2 e3 = stage[wi][i + 3];
            int2 e4 = stage[wi][i + 4];
            int2 e5 = stage[wi][i + 5];
            int2 e6 = stage[wi][i + 6];
            int2 e7 = stage[wi][i + 7];
            float2 f0 = __half22float2(reinterpret_cast<const __half2*>(g_h1 + (size_t)e0.x * F_HID)[lane]);
            float2 f1 = __half22float2(reinterpret_cast<const __half2*>(g_h1 + (size_t)e1.x * F_HID)[lane]);
            float2 f2 = __half22float2(reinterpret_cast<const __half2*>(g_h1 + (size_t)e2.x * F_HID)[lane]);
            float2 f3 = __half22float2(reinterpret_cast<const __half2*>(g_h1 + (size_t)e3.x * F_HID)[lane]);
            float2 f4 = __half22float2(reinterpret_cast<const __half2*>(g_h1 + (size_t)e4.x * F_HID)[lane]);
            float2 f5 = __half22float2(reinterpret_cast<const __half2*>(g_h1 + (size_t)e5.x * F_HID)[lane]);
            float2 f6 = __half22float2(reinterpret_cast<const __half2*>(g_h1 + (size_t)e6.x * F_HID)[lane]);
            float2 f7 = __half22float2(reinterpret_cast<const __half2*>(g_h1 + (size_t)e7.x * F_HID)[lane]);
            ax += __int_as_float(e0.y) * f0.x; ay += __int_as_float(e0.y) * f0.y;
            ax += __int_as_float(e1.y) * f1.x; ay += __int_as_float(e1.y) * f1.y;
            ax += __int_as_float(e2.y) * f2.x; ay += __int_as_float(e2.y) * f2.y;
            ax += __int_as_float(e3.y) * f3.x; ay += __int_as_float(e3.y) * f3.y;
            ax += __int_as_float(e4.y) * f4.x; ay += __int_as_float(e4.y) * f4.y;
            ax += __int_as_float(e5.y) * f5.x; ay += __int_as_float(e5.y) * f5.y;
            ax += __int_as_float(e6.y) * f6.x; ay += __int_as_float(e6.y) * f6.y;
            ax += __int_as_float(e7.y) * f7.x; ay += __int_as_float(e7.y) * f7.y;
        }
        for (; i < cnt; i++) {
            int2 e0 = stage[wi][i];
            float2 f0 = __half22float2(reinterpret_cast<const __half2*>(g_h1 + (size_t)e0.x * F_HID)[lane]);
            float n0 = __int_as_float(e0.y);
            ax += n0 * f0.x; ay += n0 * f0.y;
        }
        __syncwarp();
    }

    ax *= dv;
    ay *= dv;

    float h0 = fmaxf(ax + b1[2 * lane],     0.f);
    float h1 = fmaxf(ay + b1[2 * lane + 1], 0.f);
    float p0 = h0 * W2[(2 * lane) * 2 + 0] + h1 * W2[(2 * lane + 1) * 2 + 0];
    float p1 = h0 * W2[(2 * lane) * 2 + 1] + h1 * W2[(2 * lane + 1) * 2 + 1];
#pragma unroll
    for (int o = 16; o > 0; o >>= 1) {
        p0 += __shfl_xor_sync(0xFFFFFFFFu, p0, o);
        p1 += __shfl_xor_sync(0xFFFFFFFFu, p1, o);
    }
    if (lane == 0) {
        g_h2[w * 2 + 0] = dv * p0;   // h2' = dinv * h2
        g_h2[w * 2 + 1] = dv * p1;
    }
}

// ---------------- agg2: A = dv*(Σ ew*h2'[src] + h2'[w]) + b2; log_softmax ----------------
__global__ void __launch_bounds__(256) k_agg2(const float* __restrict__ b2,
                                              float* __restrict__ out, int n) {
    int w = (blockIdx.x * blockDim.x + threadIdx.x) >> 5;
    int lane = threadIdx.x & 31;
    if (w >= n) return;
    int2 seg = g_seg[w];
    float a0 = 0.f, a1 = 0.f;
    for (int j = seg.x + lane; j < seg.y; j += 32) {
        int2 e = g_csr[j];
        float nm = __int_as_float(e.y);
        float2 v = *reinterpret_cast<const float2*>(g_h2 + (size_t)e.x * 2);
        a0 += nm * v.x;
        a1 += nm * v.y;
    }
#pragma unroll
    for (int o = 16; o > 0; o >>= 1) {
        a0 += __shfl_xor_sync(0xFFFFFFFFu, a0, o);
        a1 += __shfl_xor_sync(0xFFFFFFFFu, a1, o);
    }
    if (lane == 0) {
        float dv = g_dinv[w];
        float2 hv = *reinterpret_cast<const float2*>(g_h2 + (size_t)w * 2);
        float A = dv * (a0 + hv.x) + b2[0];
        float B = dv * (a1 + hv.y) + b2[1];
        float m = fmaxf(A, B);
        float lse = m + logf(expf(A - m) + expf(B - m));
        out[w * 2 + 0] = A - lse;
        out[w * 2 + 1] = B - lse;
    }
}

extern "C" void kernel_launch(void* const* d_in, const int* in_sizes, int n_in,
                              void* d_out, int out_size) {
    const float* x  = (const float*)d_in[0];
    const int*   ei = (const int*)d_in[1];   // int32 (JAX x64 disabled)
    const float* ew = (const float*)d_in[2];
    const float* W1 = (const float*)d_in[3];
    const float* b1 = (const float*)d_in[4];
    const float* W2 = (const float*)d_in[5];
    const float* b2 = (const float*)d_in[6];
    float* out = (float*)d_out;

    const int n  = in_sizes[0] / F_IN;   // 100000
    const int ne = in_sizes[2];          // 3200000

    const int nq = (ne + 3) / 4;                   // 4 edges per scatter thread
    const int nblk_sc = (nq + 255) / 256;
    const int nblk_gm = (n + 15) / 16;
    k_scatter_gemm<<<nblk_sc + nblk_gm, 256>>>(ei, ew, x, W1, n, ne, nblk_sc);
    k_base<<<(n + 255) / 256, 256>>>(n);
    k_csr_fill<<<(nq + 255) / 256, 256>>>(ei, ew, ne);
    k_agg1<<<(n + 7) / 8, 256>>>(W2, b1, n);
    k_agg2<<<(n * 32 + 255) / 256, 256>>>(b2, out, n);
}

// round 12
// speedup vs baseline: 1.7365x; 1.0459x over previous
#include <cuda_runtime.h>
#include <cuda_fp16.h>
#include <cuda_bf16.h>

#define N_NODES 100000
#define N_EDGES 3200000
#define F_IN 35
#define KPAD 36
#define F_HID 64
#define F_OUT 2
#define FIXP 268435456.0f   // 2^28
#define FIXP_INV (1.0f / 268435456.0f)

// ---- scratch (static; no allocation allowed; zero-initialized at load) ----
__device__ __align__(16) __half g_h1[N_NODES * F_HID];  // dinv * (x@W1), fp16
__device__ __align__(16) float  g_h2[N_NODES * F_OUT];  // dinv * (layer-2 features)
__device__ unsigned long long g_acc[N_NODES];  // hi24: count, lo40: sum(ew)*2^28 (self-cleaned)
__device__ float g_dinv[N_NODES];
__device__ __align__(8) int2 g_seg[N_NODES];   // (beg, end) of node's CSR segment
__device__ int   g_cursor;                     // CSR cursor (self-cleaned by k_gemm_fill)
__device__ __align__(16) int g_rank[N_EDGES];  // per-edge slot within its dst segment
__device__ __align__(8) int2 g_csr[N_EDGES];   // (src, ew bits)

// ---------------- edge scatter (4 edges/thread): counts + weighted degree + rank ----
__global__ void __launch_bounds__(256) k_scatter(const int* __restrict__ ei,
                                                 const float* __restrict__ ew, int ne) {
    int e0 = (blockIdx.x * 256 + threadIdx.x) * 4;
    if (e0 + 3 < ne) {
        float4 w4 = *reinterpret_cast<const float4*>(ew + e0);  // e0 % 4 == 0
        int d0 = ei[ne + e0], d1 = ei[ne + e0 + 1];
        int d2 = ei[ne + e0 + 2], d3 = ei[ne + e0 + 3];
        unsigned long long o0 = atomicAdd(&g_acc[d0], (1ULL << 40) | (unsigned long long)(w4.x * FIXP));
        unsigned long long o1 = atomicAdd(&g_acc[d1], (1ULL << 40) | (unsigned long long)(w4.y * FIXP));
        unsigned long long o2 = atomicAdd(&g_acc[d2], (1ULL << 40) | (unsigned long long)(w4.z * FIXP));
        unsigned long long o3 = atomicAdd(&g_acc[d3], (1ULL << 40) | (unsigned long long)(w4.w * FIXP));
        *reinterpret_cast<int4*>(g_rank + e0) =
            make_int4((int)(o0 >> 40), (int)(o1 >> 40), (int)(o2 >> 40), (int)(o3 >> 40));
    } else {
        for (int e = e0; e < ne; e++) {
            int dst = ei[ne + e];
            unsigned long long old = atomicAdd(&g_acc[dst],
                (1ULL << 40) | (unsigned long long)(ew[e] * FIXP));
            g_rank[e] = (int)(old >> 40);
        }
    }
}

// ---- base: dinv + seg alloc (block scan + cursor atomic) + acc self-clean ----
__global__ void __launch_bounds__(256) k_base(int n) {
    __shared__ int swarp[8];
    __shared__ int sbase;
    int t = threadIdx.x, lane = t & 31, wid = t >> 5;
    int i = blockIdx.x * 256 + t;
    int c = 0;
    if (i < n) {
        unsigned long long a = g_acc[i];
        g_acc[i] = 0ULL;                    // self-clean for next replay
        c = (int)(a >> 40);
        float deg = 1.0f + (float)(a & ((1ULL << 40) - 1)) * FIXP_INV;
        g_dinv[i] = rsqrtf(deg);
    }
    int v = c;
#pragma unroll
    for (int o = 1; o < 32; o <<= 1) {
        int u = __shfl_up_sync(0xFFFFFFFFu, v, o);
        if (lane >= o) v += u;
    }
    if (lane == 31) swarp[wid] = v;
    __syncthreads();
    if (wid == 0) {
        int s = (lane < 8) ? swarp[lane] : 0;
#pragma unroll
        for (int o = 1; o < 8; o <<= 1) {
            int u = __shfl_up_sync(0xFFFFFFFFu, s, o);
            if (lane >= o) s += u;
        }
        if (lane < 8) swarp[lane] = s;
        if (lane == 7) sbase = atomicAdd(&g_cursor, s);
    }
    __syncthreads();
    int excl = v - c + (wid > 0 ? swarp[wid - 1] : 0);
    if (i < n) {
        int beg = sbase + excl;
        g_seg[i] = make_int2(beg, beg + c);
    }
}

// ---------------- fused: layer-1 GEMM (h1' = dinv*x@W1) || CSR fill ----------------
__global__ void __launch_bounds__(256) k_gemm_fill(
        const int* __restrict__ ei, const float* __restrict__ ew,
        const float* __restrict__ x, const float* __restrict__ W1,
        int n, int ne, int nblk_gm) {
    __shared__ float2 sW2[KPAD][32];
    __shared__ float  sx[8][2][KPAD];

    if (blockIdx.x >= (unsigned)nblk_gm) {
        // ---- CSR fill part (4 edges/thread): (src, ew) ----
        if (blockIdx.x == (unsigned)nblk_gm && threadIdx.x == 0)
            g_cursor = 0;   // self-clean (k_base of this launch already consumed it)
        int e0 = ((blockIdx.x - nblk_gm) * 256 + threadIdx.x) * 4;
        if (e0 + 3 < ne) {
            int4   s4 = *reinterpret_cast<const int4*>(ei + e0);       // e0 % 4 == 0
            float4 w4 = *reinterpret_cast<const float4*>(ew + e0);
            int4   r4 = *reinterpret_cast<const int4*>(g_rank + e0);
            int d0 = ei[ne + e0], d1 = ei[ne + e0 + 1];
            int d2 = ei[ne + e0 + 2], d3 = ei[ne + e0 + 3];
            g_csr[g_seg[d0].x + r4.x] = make_int2(s4.x, __float_as_int(w4.x));
            g_csr[g_seg[d1].x + r4.y] = make_int2(s4.y, __float_as_int(w4.y));
            g_csr[g_seg[d2].x + r4.z] = make_int2(s4.z, __float_as_int(w4.z));
            g_csr[g_seg[d3].x + r4.w] = make_int2(s4.w, __float_as_int(w4.w));
        } else {
            for (int e = e0; e < ne; e++) {
                int src = ei[e];
                int dst = ei[ne + e];
                g_csr[g_seg[dst].x + g_rank[e]] = make_int2(src, __float_as_int(ew[e]));
            }
        }
        return;
    }

    // ---- gemm1 part: h1' = dinv[row] * (x[row] @ W1), 2 rows/warp ----
    int t = threadIdx.x, w = t >> 5, lane = t & 31;
    for (int i = t; i < KPAD * 32; i += 256) {
        int k = i >> 5, l = i & 31;
        float2 v = make_float2(0.f, 0.f);
        if (k < F_IN) { v.x = W1[k * F_HID + 2 * l]; v.y = W1[k * F_HID + 2 * l + 1]; }
        sW2[k][l] = v;
    }
    int row0 = blockIdx.x * 16 + w * 2;
#pragma unroll
    for (int r = 0; r < 2; r++) {
        int row = row0 + r;
        if (row < n) {
            sx[w][r][lane] = x[(size_t)row * F_IN + lane];
            if (lane < 4) sx[w][r][32 + lane] =
                (lane < F_IN - 32) ? x[(size_t)row * F_IN + 32 + lane] : 0.f;
        }
    }
    __syncthreads();
    if (row0 >= n) return;

    float acc00 = 0.f, acc01 = 0.f, acc10 = 0.f, acc11 = 0.f;
    const float4* sx40 = reinterpret_cast<const float4*>(sx[w][0]);
    const float4* sx41 = reinterpret_cast<const float4*>(sx[w][1]);
#pragma unroll
    for (int k4 = 0; k4 < KPAD / 4; k4++) {
        float4 x0 = sx40[k4], x1 = sx41[k4];
#pragma unroll
        for (int i = 0; i < 4; i++) {
            float2 wv = sW2[k4 * 4 + i][lane];
            float xv0 = (&x0.x)[i], xv1 = (&x1.x)[i];
            acc00 += xv0 * wv.x; acc01 += xv0 * wv.y;
            acc10 += xv1 * wv.x; acc11 += xv1 * wv.y;
        }
    }
    float dv0 = g_dinv[row0];
    reinterpret_cast<__half2*>(g_h1 + (size_t)row0 * F_HID)[lane] =
        __floats2half2_rn(dv0 * acc00, dv0 * acc01);
    if (row0 + 1 < n) {
        float dv1 = g_dinv[row0 + 1];
        reinterpret_cast<__half2*>(g_h1 + (size_t)(row0 + 1) * F_HID)[lane] =
            __floats2half2_rn(dv1 * acc10, dv1 * acc11);
    }
}

// ---------------- agg1: agg = dv*(Σ ew*h1'[src] + h1'[w]); h2' = dv*GEMV ----------------
__global__ void __launch_bounds__(256) k_agg1(const float* __restrict__ W2,
                                              const float* __restrict__ b1, int n) {
    __shared__ int2 stage[8][32];
    int wi = threadIdx.x >> 5;
    int lane = threadIdx.x & 31;
    int w = blockIdx.x * 8 + wi;
    if (w >= n) return;
    int2 seg = g_seg[w];
    int beg = seg.x, end = seg.y;
    float dv = g_dinv[w];

    float2 self = __half22float2(
        reinterpret_cast<const __half2*>(g_h1 + (size_t)w * F_HID)[lane]);
    float ax = self.x, ay = self.y;   // h1'[w] = dv*h1[w]; x dv below gives dv^2*h1

    for (int j0 = beg; j0 < end; j0 += 32) {
        int j = j0 + lane;
        if (j < end) stage[wi][lane] = g_csr[j];
        __syncwarp();
        int cnt = end - j0; if (cnt > 32) cnt = 32;
        int i = 0;
        for (; i + 8 <= cnt; i += 8) {
            int2 e0 = stage[wi][i];
            int2 e1 = stage[wi][i + 1];
            int2 e2 = stage[wi][i + 2];
            int2 e3 = stage[wi][i + 3];
            int2 e4 = stage[wi][i + 4];
            int2 e5 = stage[wi][i + 5];
            int2 e6 = stage[wi][i + 6];
            int2 e7 = stage[wi][i + 7];
            float2 f0 = __half22float2(reinterpret_cast<const __half2*>(g_h1 + (size_t)e0.x * F_HID)[lane]);
            float2 f1 = __half22float2(reinterpret_cast<const __half2*>(g_h1 + (size_t)e1.x * F_HID)[lane]);
            float2 f2 = __half22float2(reinterpret_cast<const __half2*>(g_h1 + (size_t)e2.x * F_HID)[lane]);
            float2 f3 = __half22float2(reinterpret_cast<const __half2*>(g_h1 + (size_t)e3.x * F_HID)[lane]);
            float2 f4 = __half22float2(reinterpret_cast<const __half2*>(g_h1 + (size_t)e4.x * F_HID)[lane]);
            float2 f5 = __half22float2(reinterpret_cast<const __half2*>(g_h1 + (size_t)e5.x * F_HID)[lane]);
            float2 f6 = __half22float2(reinterpret_cast<const __half2*>(g_h1 + (size_t)e6.x * F_HID)[lane]);
            float2 f7 = __half22float2(reinterpret_cast<const __half2*>(g_h1 + (size_t)e7.x * F_HID)[lane]);
            ax += __int_as_float(e0.y) * f0.x; ay += __int_as_float(e0.y) * f0.y;
            ax += __int_as_float(e1.y) * f1.x; ay += __int_as_float(e1.y) * f1.y;
            ax += __int_as_float(e2.y) * f2.x; ay += __int_as_float(e2.y) * f2.y;
            ax += __int_as_float(e3.y) * f3.x; ay += __int_as_float(e3.y) * f3.y;
            ax += __int_as_float(e4.y) * f4.x; ay += __int_as_float(e4.y) * f4.y;
            ax += __int_as_float(e5.y) * f5.x; ay += __int_as_float(e5.y) * f5.y;
            ax += __int_as_float(e6.y) * f6.x; ay += __int_as_float(e6.y) * f6.y;
            ax += __int_as_float(e7.y) * f7.x; ay += __int_as_float(e7.y) * f7.y;
        }
        for (; i < cnt; i++) {
            int2 e0 = stage[wi][i];
            float2 f0 = __half22float2(reinterpret_cast<const __half2*>(g_h1 + (size_t)e0.x * F_HID)[lane]);
            float n0 = __int_as_float(e0.y);
            ax += n0 * f0.x; ay += n0 * f0.y;
        }
        __syncwarp();
    }

    ax *= dv;
    ay *= dv;

    float h0 = fmaxf(ax + b1[2 * lane],     0.f);
    float h1 = fmaxf(ay + b1[2 * lane + 1], 0.f);
    float p0 = h0 * W2[(2 * lane) * 2 + 0] + h1 * W2[(2 * lane + 1) * 2 + 0];
    float p1 = h0 * W2[(2 * lane) * 2 + 1] + h1 * W2[(2 * lane + 1) * 2 + 1];
#pragma unroll
    for (int o = 16; o > 0; o >>= 1) {
        p0 += __shfl_xor_sync(0xFFFFFFFFu, p0, o);
        p1 += __shfl_xor_sync(0xFFFFFFFFu, p1, o);
    }
    if (lane == 0) {
        g_h2[w * 2 + 0] = dv * p0;   // h2' = dinv * h2
        g_h2[w * 2 + 1] = dv * p1;
    }
}

// ---------------- agg2: A = dv*(Σ ew*h2'[src] + h2'[w]) + b2; log_softmax ----------------
__global__ void __launch_bounds__(256) k_agg2(const float* __restrict__ b2,
                                              float* __restrict__ out, int n) {
    int w = (blockIdx.x * blockDim.x + threadIdx.x) >> 5;
    int lane = threadIdx.x & 31;
    if (w >= n) return;
    int2 seg = g_seg[w];
    float a0 = 0.f, a1 = 0.f;
    for (int j = seg.x + lane; j < seg.y; j += 32) {
        int2 e = g_csr[j];
        float nm = __int_as_float(e.y);
        float2 v = *reinterpret_cast<const float2*>(g_h2 + (size_t)e.x * 2);
        a0 += nm * v.x;
        a1 += nm * v.y;
    }
#pragma unroll
    for (int o = 16; o > 0; o >>= 1) {
        a0 += __shfl_xor_sync(0xFFFFFFFFu, a0, o);
        a1 += __shfl_xor_sync(0xFFFFFFFFu, a1, o);
    }
    if (lane == 0) {
        float dv = g_dinv[w];
        float2 hv = *reinterpret_cast<const float2*>(g_h2 + (size_t)w * 2);
        float A = dv * (a0 + hv.x) + b2[0];
        float B = dv * (a1 + hv.y) + b2[1];
        float m = fmaxf(A, B);
        float lse = m + logf(expf(A - m) + expf(B - m));
        out[w * 2 + 0] = A - lse;
        out[w * 2 + 1] = B - lse;
    }
}

extern "C" void kernel_launch(void* const* d_in, const int* in_sizes, int n_in,
                              void* d_out, int out_size) {
    const float* x  = (const float*)d_in[0];
    const int*   ei = (const int*)d_in[1];   // int32 (JAX x64 disabled)
    const float* ew = (const float*)d_in[2];
    const float* W1 = (const float*)d_in[3];
    const float* b1 = (const float*)d_in[4];
    const float* W2 = (const float*)d_in[5];
    const float* b2 = (const float*)d_in[6];
    float* out = (float*)d_out;

    const int n  = in_sizes[0] / F_IN;   // 100000
    const int ne = in_sizes[2];          // 3200000

    const int nq = (ne + 3) / 4;                   // 4 edges per edge-stream thread
    const int nblk_ed = (nq + 255) / 256;
    const int nblk_gm = (n + 15) / 16;
    k_scatter<<<nblk_ed, 256>>>(ei, ew, ne);
    k_base<<<(n + 255) / 256, 256>>>(n);
    k_gemm_fill<<<nblk_gm + nblk_ed, 256>>>(ei, ew, x, W1, n, ne, nblk_gm);
    k_agg1<<<(n + 7) / 8, 256>>>(W2, b1, n);
    k_agg2<<<(n * 32 + 255) / 256, 256>>>(b2, out, n);
}